// round 1
// baseline (speedup 1.0000x reference)
#include <cuda_runtime.h>
#include <cstdint>

// Problem constants
#define B_SZ    2
#define S_LEN   2048
#define D_MODEL 1024
#define N_HEADS 16
#define HD      64
#define N3      (3 * D_MODEL)          // 3072
#define ROWS    (B_SZ * S_LEN)          // 4096
#define LORA_SCALE 0.5f                 // LORA_DIM / LORA_ALPHA = 16/32

// Scratch (allocation-free: __device__ globals)
__device__ float g_weff[D_MODEL * N3];     // 12 MB  effective c_attn weight (LoRA folded)
__device__ float g_qkv[(size_t)ROWS * N3]; // 48 MB  qkv = x @ W_eff + b
__device__ float g_attn[(size_t)ROWS * D_MODEL]; // 16 MB attention output (pre-proj)

// ---------------------------------------------------------------------------
// Kernel 1: W_eff = c_attn_w; q-cols += s * q_a1@q_a2; v-cols += s * v_a1@v_a2
// ---------------------------------------------------------------------------
__global__ void build_weff(const float* __restrict__ w,
                           const float* __restrict__ qa1, const float* __restrict__ qa2,
                           const float* __restrict__ va1, const float* __restrict__ va2) {
    int idx = blockIdx.x * blockDim.x + threadIdx.x;
    if (idx >= D_MODEL * N3) return;
    int d = idx / N3;
    int n = idx % N3;
    float val = w[idx];
    if (n < D_MODEL) {
        float s = 0.f;
        #pragma unroll
        for (int r = 0; r < 16; r++) s += qa1[d * 16 + r] * qa2[r * D_MODEL + n];
        val += LORA_SCALE * s;
    } else if (n >= 2 * D_MODEL) {
        int nn = n - 2 * D_MODEL;
        float s = 0.f;
        #pragma unroll
        for (int r = 0; r < 16; r++) s += va1[d * 16 + r] * va2[r * D_MODEL + nn];
        val += LORA_SCALE * s;
    }
    g_weff[idx] = val;
}

// ---------------------------------------------------------------------------
// Kernel 2/5: SGEMM  C[M,N] = A[M,K] @ B[K,N] + bias[N]
// 128x128x16 tile, 8x8 per thread, 256 threads. M,N,K multiples of 128/16.
// ---------------------------------------------------------------------------
__global__ __launch_bounds__(256) void sgemm_bias(
    int M, int N, int K,
    const float* __restrict__ A, const float* __restrict__ B,
    const float* __restrict__ bias, float* __restrict__ C) {
    constexpr int BM = 128, BN = 128, BK = 16, TM = 8, TN = 8;
    __shared__ float As[BK][BM];
    __shared__ float Bs[BK][BN];

    const int tid  = threadIdx.x;
    const int tCol = tid % 16;
    const int tRow = tid / 16;

    const float* Aptr = A + (size_t)blockIdx.y * BM * K;
    const float* Bptr = B + (size_t)blockIdx.x * BN;

    const int aRow = tid / 4;          // 0..63
    const int aCol = (tid % 4) * 4;    // 0,4,8,12
    const int bRow = tid / 32;         // 0..7
    const int bCol = (tid % 32) * 4;   // 0..124

    float acc[TM][TN] = {};

    for (int k0 = 0; k0 < K; k0 += BK) {
        #pragma unroll
        for (int ch = 0; ch < 2; ch++) {
            int r = aRow + ch * 64;
            float4 v = *(const float4*)(Aptr + (size_t)r * K + k0 + aCol);
            As[aCol + 0][r] = v.x; As[aCol + 1][r] = v.y;
            As[aCol + 2][r] = v.z; As[aCol + 3][r] = v.w;
        }
        #pragma unroll
        for (int ch = 0; ch < 2; ch++) {
            int r = bRow + ch * 8;
            *(float4*)(&Bs[r][bCol]) = *(const float4*)(Bptr + (size_t)(k0 + r) * N + bCol);
        }
        __syncthreads();

        #pragma unroll
        for (int k = 0; k < BK; k++) {
            float am[TM], bn[TN];
            #pragma unroll
            for (int i = 0; i < TM; i++) am[i] = As[k][tRow * TM + i];
            #pragma unroll
            for (int j = 0; j < TN; j++) bn[j] = Bs[k][tCol * TN + j];
            #pragma unroll
            for (int i = 0; i < TM; i++)
                #pragma unroll
                for (int j = 0; j < TN; j++)
                    acc[i][j] = fmaf(am[i], bn[j], acc[i][j]);
        }
        __syncthreads();
    }

    #pragma unroll
    for (int i = 0; i < TM; i++) {
        size_t row = (size_t)blockIdx.y * BM + tRow * TM + i;
        #pragma unroll
        for (int j = 0; j < TN; j += 4) {
            int col = blockIdx.x * BN + tCol * TN + j;
            float4 v;
            v.x = acc[i][j + 0] + bias[col + 0];
            v.y = acc[i][j + 1] + bias[col + 1];
            v.z = acc[i][j + 2] + bias[col + 2];
            v.w = acc[i][j + 3] + bias[col + 3];
            *(float4*)(C + row * N + col) = v;
        }
    }
}

// ---------------------------------------------------------------------------
// Kernel 3: scatter K,V from qkv into present[2,B,H,S,hd] (in d_out)
// ---------------------------------------------------------------------------
__global__ void scatter_kv(float* __restrict__ present) {
    int idx = blockIdx.x * blockDim.x + threadIdx.x;
    if (idx >= 2 * B_SZ * N_HEADS * S_LEN * HD) return;
    // present linear layout: c,b,h,s,d
    int d = idx & 63;
    int s = (idx >> 6) & (S_LEN - 1);
    int h = (idx >> 17) & (N_HEADS - 1);
    int b = (idx >> 21) & (B_SZ - 1);
    int c = idx >> 22;  // 0 = k, 1 = v
    present[idx] = g_qkv[(size_t)(b * S_LEN + s) * N3 + D_MODEL + c * D_MODEL + h * HD + d];
}

// ---------------------------------------------------------------------------
// Kernel 4: causal flash attention, fp32, BM=BN=64, hd=64, 256 threads.
// Q read from g_qkv (cols 0..1023), K/V read from present (contiguous per head).
// Online softmax matches reference (masked scores -> exp -> 0).
// ---------------------------------------------------------------------------
__global__ __launch_bounds__(256) void flash_attn(const float* __restrict__ present) {
    extern __shared__ float sm[];
    float* Qs = sm;               // 64 x 65 (padded)
    float* Ks = Qs + 64 * 65;     // 64 x 65 (padded; reused for P tile)
    float* Vs = Ks + 64 * 65;     // 64 x 64

    const int bh = blockIdx.y;            // b*16 + h
    const int b  = bh >> 4;
    const int h  = bh & 15;
    const int q0 = blockIdx.x * 64;
    const int tid = threadIdx.x;
    const int tx  = tid & 15;             // 0..15 -> 4 cols each
    const int ty  = tid >> 4;             // 0..15 -> 4 rows each

    // Load Q tile, pre-scaled by 1/sqrt(hd)=0.125
    for (int i = tid; i < 64 * 64; i += 256) {
        int r = i >> 6, c = i & 63;
        Qs[r * 65 + c] =
            g_qkv[(size_t)(b * S_LEN + q0 + r) * N3 + h * HD + c] * 0.125f;
    }

    const float* Kbase = present + ((size_t)(b * N_HEADS + h)) * S_LEN * HD;
    const float* Vbase = present + ((size_t)((2 + b) * N_HEADS + h)) * S_LEN * HD;

    float acc[4][4] = {};
    float m_i[4], l_i[4];
    #pragma unroll
    for (int i = 0; i < 4; i++) { m_i[i] = -1e30f; l_i[i] = 0.f; }

    const int nTiles = blockIdx.x + 1;    // causal: keys up to and incl. diagonal
    for (int t = 0; t < nTiles; t++) {
        const int k0 = t * 64;
        __syncthreads();   // prior iteration done reading Ks(P)/Vs
        for (int i = tid; i < 64 * 64; i += 256) {
            int r = i >> 6, c = i & 63;
            Ks[r * 65 + c] = Kbase[(size_t)(k0 + r) * HD + c];
            Vs[r * 64 + c] = Vbase[(size_t)(k0 + r) * HD + c];
        }
        __syncthreads();

        // S = Q K^T  (4x4 per thread)
        float s[4][4] = {};
        for (int k = 0; k < 64; k++) {
            float qf[4], kf[4];
            #pragma unroll
            for (int i = 0; i < 4; i++) qf[i] = Qs[(ty * 4 + i) * 65 + k];
            #pragma unroll
            for (int j = 0; j < 4; j++) kf[j] = Ks[(tx * 4 + j) * 65 + k];
            #pragma unroll
            for (int i = 0; i < 4; i++)
                #pragma unroll
                for (int j = 0; j < 4; j++)
                    s[i][j] = fmaf(qf[i], kf[j], s[i][j]);
        }

        // Causal mask needed only on the diagonal tile
        if (t == nTiles - 1) {
            #pragma unroll
            for (int i = 0; i < 4; i++)
                #pragma unroll
                for (int j = 0; j < 4; j++)
                    if (k0 + tx * 4 + j > q0 + ty * 4 + i) s[i][j] = -1e30f;
        }

        // Online softmax (row reductions over the 16 tx-threads via shfl)
        float p[4][4];
        #pragma unroll
        for (int i = 0; i < 4; i++) {
            float rmax = s[i][0];
            #pragma unroll
            for (int j = 1; j < 4; j++) rmax = fmaxf(rmax, s[i][j]);
            #pragma unroll
            for (int off = 8; off >= 1; off >>= 1)
                rmax = fmaxf(rmax, __shfl_xor_sync(0xffffffffu, rmax, off));
            float newm = fmaxf(m_i[i], rmax);
            float corr = __expf(m_i[i] - newm);
            m_i[i] = newm;
            float rsum = 0.f;
            #pragma unroll
            for (int j = 0; j < 4; j++) { p[i][j] = __expf(s[i][j] - newm); rsum += p[i][j]; }
            #pragma unroll
            for (int off = 8; off >= 1; off >>= 1)
                rsum += __shfl_xor_sync(0xffffffffu, rsum, off);
            l_i[i] = l_i[i] * corr + rsum;
            #pragma unroll
            for (int j = 0; j < 4; j++) acc[i][j] *= corr;
        }

        // Stage P into the K buffer, then O += P @ V
        __syncthreads();
        #pragma unroll
        for (int i = 0; i < 4; i++)
            #pragma unroll
            for (int j = 0; j < 4; j++)
                Ks[(ty * 4 + i) * 65 + tx * 4 + j] = p[i][j];
        __syncthreads();

        for (int n = 0; n < 64; n++) {
            float4 vf = *(const float4*)(&Vs[n * 64 + tx * 4]);
            #pragma unroll
            for (int i = 0; i < 4; i++) {
                float pv = Ks[(ty * 4 + i) * 65 + n];
                acc[i][0] = fmaf(pv, vf.x, acc[i][0]);
                acc[i][1] = fmaf(pv, vf.y, acc[i][1]);
                acc[i][2] = fmaf(pv, vf.z, acc[i][2]);
                acc[i][3] = fmaf(pv, vf.w, acc[i][3]);
            }
        }
    }

    #pragma unroll
    for (int i = 0; i < 4; i++) {
        float inv = 1.0f / l_i[i];
        size_t row = (size_t)(b * S_LEN + q0 + ty * 4 + i);
        float4 v;
        v.x = acc[i][0] * inv; v.y = acc[i][1] * inv;
        v.z = acc[i][2] * inv; v.w = acc[i][3] * inv;
        *(float4*)(g_attn + row * D_MODEL + h * HD + tx * 4) = v;
    }
}

// ---------------------------------------------------------------------------
extern "C" void kernel_launch(void* const* d_in, const int* in_sizes, int n_in,
                              void* d_out, int out_size) {
    const float* x        = (const float*)d_in[0];
    const float* c_attn_w = (const float*)d_in[1];
    const float* c_attn_b = (const float*)d_in[2];
    const float* c_proj_w = (const float*)d_in[3];
    const float* c_proj_b = (const float*)d_in[4];
    const float* q_a1     = (const float*)d_in[5];
    const float* q_a2     = (const float*)d_in[6];
    const float* v_a1     = (const float*)d_in[7];
    const float* v_a2     = (const float*)d_in[8];

    float* out     = (float*)d_out;
    float* a_out   = out;                                   // [B,S,D]
    float* present = out + (size_t)ROWS * D_MODEL;          // [2,B,H,S,hd]

    float *weff, *qkv, *attn;
    cudaGetSymbolAddress((void**)&weff, g_weff);
    cudaGetSymbolAddress((void**)&qkv,  g_qkv);
    cudaGetSymbolAddress((void**)&attn, g_attn);

    // 1) Fold LoRA into the QKV weight
    build_weff<<<(D_MODEL * N3 + 255) / 256, 256>>>(c_attn_w, q_a1, q_a2, v_a1, v_a2);

    // 2) qkv = x @ W_eff + c_attn_b
    sgemm_bias<<<dim3(N3 / 128, ROWS / 128), 256>>>(
        ROWS, N3, D_MODEL, x, weff, c_attn_b, qkv);

    // 3) present[2,B,H,S,hd] <- k,v
    scatter_kv<<<(2 * ROWS * D_MODEL + 255) / 256, 256>>>(present);

    // 4) causal flash attention
    const int smem = (64 * 65 * 2 + 64 * 64) * (int)sizeof(float);  // 49664 B
    cudaFuncSetAttribute(flash_attn, cudaFuncAttributeMaxDynamicSharedMemorySize, smem);
    flash_attn<<<dim3(S_LEN / 64, B_SZ * N_HEADS), 256, smem>>>(present);

    // 5) a = attn @ c_proj_w + c_proj_b
    sgemm_bias<<<dim3(D_MODEL / 128, ROWS / 128), 256>>>(
        ROWS, D_MODEL, D_MODEL, attn, c_proj_w, c_proj_b, a_out);
}

// round 3
// speedup vs baseline: 1.2743x; 1.2743x over previous
#include <cuda_runtime.h>
#include <cuda_bf16.h>
#include <cstdint>

// ---------------------------------------------------------------- constants
#define B_SZ    2
#define S_LEN   2048
#define D_MODEL 1024
#define N_HEADS 16
#define HD      64
#define N3      (3 * D_MODEL)          // 3072
#define ROWS    (B_SZ * S_LEN)          // 4096
#define LORA_SCALE 0.5f

// ---------------------------------------------------------------- scratch
__device__ float g_weffT[(size_t)N3 * D_MODEL];      // 12 MB  [N3, D]
__device__ float g_projT[(size_t)D_MODEL * D_MODEL]; // 4 MB   [D, D]
__device__ float g_qkv[(size_t)ROWS * N3];           // 48 MB
__device__ float g_attn[(size_t)ROWS * D_MODEL];     // 16 MB

// ---------------------------------------------------------------- helpers
__device__ __forceinline__ uint32_t smem_u32(const void* p) {
    uint32_t a;
    asm("{ .reg .u64 t; cvta.to.shared.u64 t, %1; cvt.u32.u64 %0, t; }" : "=r"(a) : "l"(p));
    return a;
}

#define LDM4(r, addr)                                                        \
    asm volatile("ldmatrix.sync.aligned.m8n8.x4.shared.b16 {%0,%1,%2,%3}, [%4];" \
        : "=r"((r)[0]), "=r"((r)[1]), "=r"((r)[2]), "=r"((r)[3]) : "r"(addr))

#define MMA_BF16(d, a, b0, b1)                                               \
    asm volatile("mma.sync.aligned.m16n8k16.row.col.f32.bf16.bf16.f32 "      \
        "{%0,%1,%2,%3}, {%4,%5,%6,%7}, {%8,%9}, {%0,%1,%2,%3};"              \
        : "+f"((d)[0]), "+f"((d)[1]), "+f"((d)[2]), "+f"((d)[3])             \
        : "r"((a)[0]), "r"((a)[1]), "r"((a)[2]), "r"((a)[3]),                \
          "r"(b0), "r"(b1))

// fp32 -> (bf16 hi, bf16 lo) split; pack float4 -> two uint2 (4 bf16 each)
__device__ __forceinline__ void split_pack(float4 v, uint2& hi, uint2& lo) {
    __nv_bfloat16 h0 = __float2bfloat16(v.x);
    __nv_bfloat16 h1 = __float2bfloat16(v.y);
    __nv_bfloat16 h2 = __float2bfloat16(v.z);
    __nv_bfloat16 h3 = __float2bfloat16(v.w);
    __nv_bfloat16 l0 = __float2bfloat16(v.x - __bfloat162float(h0));
    __nv_bfloat16 l1 = __float2bfloat16(v.y - __bfloat162float(h1));
    __nv_bfloat16 l2 = __float2bfloat16(v.z - __bfloat162float(h2));
    __nv_bfloat16 l3 = __float2bfloat16(v.w - __bfloat162float(h3));
    hi.x = ((uint32_t)__bfloat16_as_ushort(h1) << 16) | __bfloat16_as_ushort(h0);
    hi.y = ((uint32_t)__bfloat16_as_ushort(h3) << 16) | __bfloat16_as_ushort(h2);
    lo.x = ((uint32_t)__bfloat16_as_ushort(l1) << 16) | __bfloat16_as_ushort(l0);
    lo.y = ((uint32_t)__bfloat16_as_ushort(l3) << 16) | __bfloat16_as_ushort(l2);
}

// ---------------------------------------------------------------- transposes
__global__ __launch_bounds__(1024) void build_weffT(
    const float* __restrict__ w,
    const float* __restrict__ qa1, const float* __restrict__ qa2,
    const float* __restrict__ va1, const float* __restrict__ va2) {
    __shared__ float t[32][33];
    int tx = threadIdx.x, ty = threadIdx.y;
    int n0 = blockIdx.x * 32, d0 = blockIdx.y * 32;
    int d = d0 + ty, n = n0 + tx;
    float val = w[(size_t)d * N3 + n];
    if (n < D_MODEL) {
        float s = 0.f;
        #pragma unroll
        for (int r = 0; r < 16; r++) s += qa1[d * 16 + r] * qa2[r * D_MODEL + n];
        val += LORA_SCALE * s;
    } else if (n >= 2 * D_MODEL) {
        int nn = n - 2 * D_MODEL;
        float s = 0.f;
        #pragma unroll
        for (int r = 0; r < 16; r++) s += va1[d * 16 + r] * va2[r * D_MODEL + nn];
        val += LORA_SCALE * s;
    }
    t[ty][tx] = val;
    __syncthreads();
    g_weffT[(size_t)(n0 + ty) * D_MODEL + d0 + tx] = t[tx][ty];
}

__global__ __launch_bounds__(1024) void build_projT(const float* __restrict__ w) {
    __shared__ float t[32][33];
    int tx = threadIdx.x, ty = threadIdx.y;
    int n0 = blockIdx.x * 32, d0 = blockIdx.y * 32;
    t[ty][tx] = w[(size_t)(d0 + ty) * D_MODEL + n0 + tx];
    __syncthreads();
    g_projT[(size_t)(n0 + ty) * D_MODEL + d0 + tx] = t[tx][ty];
}

// ---------------------------------------------------------------- mma GEMM
// C[M,N] = A[M,K] @ BT[N,K]^T + bias, fp32 in/out via 2-term bf16 split.
// Tile 128x128x32, 8 warps (4 x m, 2 x n), warp tile 32x64.
// smem: rows with 80-byte pitch (32 bf16 = 64B data + 16B pad) -> ldmatrix
// row addresses cover all 32 banks (80B = 20 banks).
#define GP          80          // row pitch bytes
#define OFF_AHI     0
#define OFF_ALO     10240
#define OFF_BHI     20480
#define OFF_BLO     30720
#define GBUF        40960
#define G_SMEM      (2 * GBUF)  // 81920

__global__ __launch_bounds__(256, 1) void mma_gemm(
    int N, int K,
    const float* __restrict__ A, const float* __restrict__ BT,
    const float* __restrict__ bias, float* __restrict__ C) {
    extern __shared__ char smraw[];
    const uint32_t sbase = smem_u32(smraw);

    const int tid  = threadIdx.x;
    const int wid  = tid >> 5;
    const int lane = tid & 31;
    const int wm   = wid & 3;       // m-warp: rows wm*32
    const int wn   = wid >> 2;      // n-warp: cols wn*64
    const int m0   = blockIdx.y * 128;
    const int n0   = blockIdx.x * 128;

    const float* Ag = A  + (size_t)m0 * K;
    const float* Bg = BT + (size_t)n0 * K;
    const int NK = K / 32;

    // loader state
    const int lr_  = tid >> 3;          // row 0..31 step: idx/8
    float4 stA[4], stB[4];

    auto ldg_tile = [&](int kt) {
        #pragma unroll
        for (int j = 0; j < 4; j++) {
            int idx = tid + j * 256;
            int r = idx >> 3, c4 = idx & 7;
            stA[j] = *(const float4*)(Ag + (size_t)r * K + kt * 32 + c4 * 4);
            stB[j] = *(const float4*)(Bg + (size_t)r * K + kt * 32 + c4 * 4);
        }
    };
    auto sts_tile = [&](int bf) {
        char* buf = smraw + bf * GBUF;
        #pragma unroll
        for (int j = 0; j < 4; j++) {
            int idx = tid + j * 256;
            int r = idx >> 3, c4 = idx & 7;
            uint2 hi, lo;
            split_pack(stA[j], hi, lo);
            *(uint2*)(buf + OFF_AHI + r * GP + c4 * 8) = hi;
            *(uint2*)(buf + OFF_ALO + r * GP + c4 * 8) = lo;
            split_pack(stB[j], hi, lo);
            *(uint2*)(buf + OFF_BHI + r * GP + c4 * 8) = hi;
            *(uint2*)(buf + OFF_BLO + r * GP + c4 * 8) = lo;
        }
    };

    float acc[2][8][4];
    #pragma unroll
    for (int i = 0; i < 2; i++)
        #pragma unroll
        for (int j = 0; j < 8; j++)
            #pragma unroll
            for (int k = 0; k < 4; k++) acc[i][j][k] = 0.f;

    // ldmatrix lane addressing
    const int g   = lane >> 3;
    const int lr  = lane & 7;
    const int rowsel = ((g & 1) << 3) + lr;       // +0/+8 row within atom
    const int kg  = (g >> 1) << 4;                // +0/+16 bytes (k 0-7 / 8-15)

    ldg_tile(0);
    sts_tile(0);
    __syncthreads();

    for (int kt = 0; kt < NK; kt++) {
        if (kt + 1 < NK) ldg_tile(kt + 1);

        const uint32_t bufb = sbase + (kt & 1) * GBUF;
        #pragma unroll
        for (int ks = 0; ks < 2; ks++) {
            const uint32_t koff = ks * 32 + kg;
            uint32_t a_hi[2][4], a_lo[2][4];
            #pragma unroll
            for (int am = 0; am < 2; am++) {
                uint32_t ad = bufb + OFF_AHI + (wm * 32 + am * 16 + rowsel) * GP + koff;
                LDM4(a_hi[am], ad);
                LDM4(a_lo[am], ad + (OFF_ALO - OFF_AHI));
            }
            #pragma unroll
            for (int bp = 0; bp < 4; bp++) {
                uint32_t bd = bufb + OFF_BHI + (wn * 64 + bp * 16 + rowsel) * GP + koff;
                uint32_t bh[4], bl[4];
                LDM4(bh, bd);
                LDM4(bl, bd + (OFF_BLO - OFF_BHI));
                #pragma unroll
                for (int am = 0; am < 2; am++) {
                    #pragma unroll
                    for (int sub = 0; sub < 2; sub++) {
                        float* d = acc[am][bp * 2 + sub];
                        MMA_BF16(d, a_hi[am], bh[sub], bh[2 + sub]);
                        MMA_BF16(d, a_hi[am], bl[sub], bl[2 + sub]);
                        MMA_BF16(d, a_lo[am], bh[sub], bh[2 + sub]);
                    }
                }
            }
        }
        if (kt + 1 < NK) {
            sts_tile((kt + 1) & 1);
            __syncthreads();
        }
    }

    // epilogue: acc[am][bn]: c0,c1 row=base+lane/4 cols 2*(lane%4)+{0,1}; c2,c3 row+8
    const int rbase = m0 + wm * 32 + (lane >> 2);
    const int cbase = n0 + wn * 64 + (lane & 3) * 2;
    #pragma unroll
    for (int am = 0; am < 2; am++) {
        #pragma unroll
        for (int bn = 0; bn < 8; bn++) {
            int col = cbase + bn * 8;
            float b0 = bias[col], b1 = bias[col + 1];
            int r0 = rbase + am * 16;
            float2 v0 = make_float2(acc[am][bn][0] + b0, acc[am][bn][1] + b1);
            float2 v1 = make_float2(acc[am][bn][2] + b0, acc[am][bn][3] + b1);
            *(float2*)(C + (size_t)r0 * N + col)       = v0;
            *(float2*)(C + (size_t)(r0 + 8) * N + col) = v1;
        }
    }
}

// ---------------------------------------------------------------- scatter K,V
__global__ void scatter_kv(float* __restrict__ present) {
    int idx = blockIdx.x * blockDim.x + threadIdx.x;
    if (idx >= 2 * B_SZ * N_HEADS * S_LEN * HD) return;
    int d = idx & 63;
    int s = (idx >> 6) & (S_LEN - 1);
    int h = (idx >> 17) & (N_HEADS - 1);
    int b = (idx >> 21) & (B_SZ - 1);
    int c = idx >> 22;
    present[idx] = g_qkv[(size_t)(b * S_LEN + s) * N3 + D_MODEL + c * D_MODEL + h * HD + d];
}

// ---------------------------------------------------------------- flash attention
__global__ __launch_bounds__(256) void flash_attn(const float* __restrict__ present) {
    extern __shared__ float sm[];
    float* Qs = sm;
    float* Ks = Qs + 64 * 65;
    float* Vs = Ks + 64 * 65;

    const int bh = blockIdx.y;
    const int b  = bh >> 4;
    const int h  = bh & 15;
    const int q0 = blockIdx.x * 64;
    const int tid = threadIdx.x;
    const int tx  = tid & 15;
    const int ty  = tid >> 4;

    for (int i = tid; i < 64 * 64; i += 256) {
        int r = i >> 6, c = i & 63;
        Qs[r * 65 + c] =
            g_qkv[(size_t)(b * S_LEN + q0 + r) * N3 + h * HD + c] * 0.125f;
    }

    const float* Kbase = present + ((size_t)(b * N_HEADS + h)) * S_LEN * HD;
    const float* Vbase = present + ((size_t)((2 + b) * N_HEADS + h)) * S_LEN * HD;

    float acc[4][4] = {};
    float m_i[4], l_i[4];
    #pragma unroll
    for (int i = 0; i < 4; i++) { m_i[i] = -1e30f; l_i[i] = 0.f; }

    const int nTiles = blockIdx.x + 1;
    for (int t = 0; t < nTiles; t++) {
        const int k0 = t * 64;
        __syncthreads();
        for (int i = tid; i < 64 * 64; i += 256) {
            int r = i >> 6, c = i & 63;
            Ks[r * 65 + c] = Kbase[(size_t)(k0 + r) * HD + c];
            Vs[r * 64 + c] = Vbase[(size_t)(k0 + r) * HD + c];
        }
        __syncthreads();

        float s[4][4] = {};
        for (int k = 0; k < 64; k++) {
            float qf[4], kf[4];
            #pragma unroll
            for (int i = 0; i < 4; i++) qf[i] = Qs[(ty * 4 + i) * 65 + k];
            #pragma unroll
            for (int j = 0; j < 4; j++) kf[j] = Ks[(tx * 4 + j) * 65 + k];
            #pragma unroll
            for (int i = 0; i < 4; i++)
                #pragma unroll
                for (int j = 0; j < 4; j++)
                    s[i][j] = fmaf(qf[i], kf[j], s[i][j]);
        }

        if (t == nTiles - 1) {
            #pragma unroll
            for (int i = 0; i < 4; i++)
                #pragma unroll
                for (int j = 0; j < 4; j++)
                    if (k0 + tx * 4 + j > q0 + ty * 4 + i) s[i][j] = -1e30f;
        }

        float p[4][4];
        #pragma unroll
        for (int i = 0; i < 4; i++) {
            float rmax = s[i][0];
            #pragma unroll
            for (int j = 1; j < 4; j++) rmax = fmaxf(rmax, s[i][j]);
            #pragma unroll
            for (int off = 8; off >= 1; off >>= 1)
                rmax = fmaxf(rmax, __shfl_xor_sync(0xffffffffu, rmax, off));
            float newm = fmaxf(m_i[i], rmax);
            float corr = __expf(m_i[i] - newm);
            m_i[i] = newm;
            float rsum = 0.f;
            #pragma unroll
            for (int j = 0; j < 4; j++) { p[i][j] = __expf(s[i][j] - newm); rsum += p[i][j]; }
            #pragma unroll
            for (int off = 8; off >= 1; off >>= 1)
                rsum += __shfl_xor_sync(0xffffffffu, rsum, off);
            l_i[i] = l_i[i] * corr + rsum;
            #pragma unroll
            for (int j = 0; j < 4; j++) acc[i][j] *= corr;
        }

        __syncthreads();
        #pragma unroll
        for (int i = 0; i < 4; i++)
            #pragma unroll
            for (int j = 0; j < 4; j++)
                Ks[(ty * 4 + i) * 65 + tx * 4 + j] = p[i][j];
        __syncthreads();

        for (int n = 0; n < 64; n++) {
            float4 vf = *(const float4*)(&Vs[n * 64 + tx * 4]);
            #pragma unroll
            for (int i = 0; i < 4; i++) {
                float pv = Ks[(ty * 4 + i) * 65 + n];
                acc[i][0] = fmaf(pv, vf.x, acc[i][0]);
                acc[i][1] = fmaf(pv, vf.y, acc[i][1]);
                acc[i][2] = fmaf(pv, vf.z, acc[i][2]);
                acc[i][3] = fmaf(pv, vf.w, acc[i][3]);
            }
        }
    }

    #pragma unroll
    for (int i = 0; i < 4; i++) {
        float inv = 1.0f / l_i[i];
        size_t row = (size_t)(b * S_LEN + q0 + ty * 4 + i);
        float4 v;
        v.x = acc[i][0] * inv; v.y = acc[i][1] * inv;
        v.z = acc[i][2] * inv; v.w = acc[i][3] * inv;
        *(float4*)(g_attn + row * D_MODEL + h * HD + tx * 4) = v;
    }
}

// ---------------------------------------------------------------- launcher
extern "C" void kernel_launch(void* const* d_in, const int* in_sizes, int n_in,
                              void* d_out, int out_size) {
    const float* x        = (const float*)d_in[0];
    const float* c_attn_w = (const float*)d_in[1];
    const float* c_attn_b = (const float*)d_in[2];
    const float* c_proj_w = (const float*)d_in[3];
    const float* c_proj_b = (const float*)d_in[4];
    const float* q_a1     = (const float*)d_in[5];
    const float* q_a2     = (const float*)d_in[6];
    const float* v_a1     = (const float*)d_in[7];
    const float* v_a2     = (const float*)d_in[8];

    float* out     = (float*)d_out;
    float* a_out   = out;
    float* present = out + (size_t)ROWS * D_MODEL;

    float *weffT, *projT, *qkv, *attn;
    cudaGetSymbolAddress((void**)&weffT, g_weffT);
    cudaGetSymbolAddress((void**)&projT, g_projT);
    cudaGetSymbolAddress((void**)&qkv,   g_qkv);
    cudaGetSymbolAddress((void**)&attn,  g_attn);

    const int fsmem = (64 * 65 * 2 + 64 * 64) * (int)sizeof(float);
    cudaFuncSetAttribute(mma_gemm, cudaFuncAttributeMaxDynamicSharedMemorySize, G_SMEM);
    cudaFuncSetAttribute(flash_attn, cudaFuncAttributeMaxDynamicSharedMemorySize, fsmem);

    // 1) transposed effective weights
    build_weffT<<<dim3(N3 / 32, D_MODEL / 32), dim3(32, 32)>>>(c_attn_w, q_a1, q_a2, v_a1, v_a2);
    build_projT<<<dim3(D_MODEL / 32, D_MODEL / 32), dim3(32, 32)>>>(c_proj_w);

    // 2) qkv = x @ W_eff + b   (bf16-split mma.sync)
    mma_gemm<<<dim3(N3 / 128, ROWS / 128), 256, G_SMEM>>>(
        N3, D_MODEL, x, weffT, c_attn_b, qkv);

    // 3) present
    scatter_kv<<<(2 * ROWS * D_MODEL + 255) / 256, 256>>>(present);

    // 4) attention
    flash_attn<<<dim3(S_LEN / 64, B_SZ * N_HEADS), 256, fsmem>>>(present);

    // 5) a = attn @ c_proj_w + b   (bf16-split mma.sync)
    mma_gemm<<<dim3(D_MODEL / 128, ROWS / 128), 256, G_SMEM>>>(
        D_MODEL, D_MODEL, attn, projT, c_proj_b, a_out);
}

// round 4
// speedup vs baseline: 1.9711x; 1.5468x over previous
#include <cuda_runtime.h>
#include <cuda_bf16.h>
#include <cstdint>

// ---------------------------------------------------------------- constants
#define B_SZ    2
#define S_LEN   2048
#define D_MODEL 1024
#define N_HEADS 16
#define HD      64
#define N3      (3 * D_MODEL)          // 3072
#define ROWS    (B_SZ * S_LEN)          // 4096
#define LORA_SCALE 0.5f

// ---------------------------------------------------------------- scratch
__device__ float g_weffT[(size_t)N3 * D_MODEL];      // 12 MB  [N3, D]
__device__ float g_projT[(size_t)D_MODEL * D_MODEL]; // 4 MB   [D, D]
__device__ float g_qkv[(size_t)ROWS * N3];           // 48 MB
__device__ float g_attn[(size_t)ROWS * D_MODEL];     // 16 MB

// ---------------------------------------------------------------- helpers
__device__ __forceinline__ uint32_t smem_u32(const void* p) {
    uint32_t a;
    asm("{ .reg .u64 t; cvta.to.shared.u64 t, %1; cvt.u32.u64 %0, t; }" : "=r"(a) : "l"(p));
    return a;
}

#define LDM4(r, addr)                                                        \
    asm volatile("ldmatrix.sync.aligned.m8n8.x4.shared.b16 {%0,%1,%2,%3}, [%4];" \
        : "=r"((r)[0]), "=r"((r)[1]), "=r"((r)[2]), "=r"((r)[3]) : "r"(addr))

#define LDM4T(r, addr)                                                       \
    asm volatile("ldmatrix.sync.aligned.m8n8.x4.trans.shared.b16 {%0,%1,%2,%3}, [%4];" \
        : "=r"((r)[0]), "=r"((r)[1]), "=r"((r)[2]), "=r"((r)[3]) : "r"(addr))

#define MMA_BF16(d, a, b0, b1)                                               \
    asm volatile("mma.sync.aligned.m16n8k16.row.col.f32.bf16.bf16.f32 "      \
        "{%0,%1,%2,%3}, {%4,%5,%6,%7}, {%8,%9}, {%0,%1,%2,%3};"              \
        : "+f"((d)[0]), "+f"((d)[1]), "+f"((d)[2]), "+f"((d)[3])             \
        : "r"((a)[0]), "r"((a)[1]), "r"((a)[2]), "r"((a)[3]),                \
          "r"(b0), "r"(b1))

// fp32 -> (bf16 hi, bf16 lo) split; pack float4 -> two uint2 (4 bf16 each)
__device__ __forceinline__ void split_pack(float4 v, uint2& hi, uint2& lo) {
    __nv_bfloat16 h0 = __float2bfloat16(v.x);
    __nv_bfloat16 h1 = __float2bfloat16(v.y);
    __nv_bfloat16 h2 = __float2bfloat16(v.z);
    __nv_bfloat16 h3 = __float2bfloat16(v.w);
    __nv_bfloat16 l0 = __float2bfloat16(v.x - __bfloat162float(h0));
    __nv_bfloat16 l1 = __float2bfloat16(v.y - __bfloat162float(h1));
    __nv_bfloat16 l2 = __float2bfloat16(v.z - __bfloat162float(h2));
    __nv_bfloat16 l3 = __float2bfloat16(v.w - __bfloat162float(h3));
    hi.x = ((uint32_t)__bfloat16_as_ushort(h1) << 16) | __bfloat16_as_ushort(h0);
    hi.y = ((uint32_t)__bfloat16_as_ushort(h3) << 16) | __bfloat16_as_ushort(h2);
    lo.x = ((uint32_t)__bfloat16_as_ushort(l1) << 16) | __bfloat16_as_ushort(l0);
    lo.y = ((uint32_t)__bfloat16_as_ushort(l3) << 16) | __bfloat16_as_ushort(l2);
}

__device__ __forceinline__ uint32_t pack2bf(float a, float b) {
    return ((uint32_t)__bfloat16_as_ushort(__float2bfloat16(b)) << 16) |
           __bfloat16_as_ushort(__float2bfloat16(a));
}

// fast 2^t for t <= 0, FMA-pipe only (no MUFU). rel err ~2.4e-6.
__device__ __forceinline__ float exp2_fast(float t) {
    t = fmaxf(t, -126.0f);
    float r = t + 12582912.0f;              // round-to-nearest integer
    float f = t - (r - 12582912.0f);        // f in [-0.5, 0.5]
    int n_i = __float_as_int(r) - 0x4B400000;
    float p = 1.3333558e-3f;
    p = fmaf(p, f, 9.6181291e-3f);
    p = fmaf(p, f, 5.5504109e-2f);
    p = fmaf(p, f, 2.4022651e-1f);
    p = fmaf(p, f, 6.9314718e-1f);
    p = fmaf(p, f, 1.0f);
    return p * __int_as_float((n_i + 127) << 23);
}

// ---------------------------------------------------------------- transposes
__global__ __launch_bounds__(1024) void build_weffT(
    const float* __restrict__ w,
    const float* __restrict__ qa1, const float* __restrict__ qa2,
    const float* __restrict__ va1, const float* __restrict__ va2) {
    __shared__ float t[32][33];
    int tx = threadIdx.x, ty = threadIdx.y;
    int n0 = blockIdx.x * 32, d0 = blockIdx.y * 32;
    int d = d0 + ty, n = n0 + tx;
    float val = w[(size_t)d * N3 + n];
    if (n < D_MODEL) {
        float s = 0.f;
        #pragma unroll
        for (int r = 0; r < 16; r++) s += qa1[d * 16 + r] * qa2[r * D_MODEL + n];
        val += LORA_SCALE * s;
    } else if (n >= 2 * D_MODEL) {
        int nn = n - 2 * D_MODEL;
        float s = 0.f;
        #pragma unroll
        for (int r = 0; r < 16; r++) s += va1[d * 16 + r] * va2[r * D_MODEL + nn];
        val += LORA_SCALE * s;
    }
    t[ty][tx] = val;
    __syncthreads();
    g_weffT[(size_t)(n0 + ty) * D_MODEL + d0 + tx] = t[tx][ty];
}

__global__ __launch_bounds__(1024) void build_projT(const float* __restrict__ w) {
    __shared__ float t[32][33];
    int tx = threadIdx.x, ty = threadIdx.y;
    int n0 = blockIdx.x * 32, d0 = blockIdx.y * 32;
    t[ty][tx] = w[(size_t)(d0 + ty) * D_MODEL + n0 + tx];
    __syncthreads();
    g_projT[(size_t)(n0 + ty) * D_MODEL + d0 + tx] = t[tx][ty];
}

// ---------------------------------------------------------------- mma GEMM (unchanged, passing)
#define GP          80
#define OFF_AHI     0
#define OFF_ALO     10240
#define OFF_BHI     20480
#define OFF_BLO     30720
#define GBUF        40960
#define G_SMEM      (2 * GBUF)

__global__ __launch_bounds__(256, 1) void mma_gemm(
    int N, int K,
    const float* __restrict__ A, const float* __restrict__ BT,
    const float* __restrict__ bias, float* __restrict__ C) {
    extern __shared__ char smraw[];
    const uint32_t sbase = smem_u32(smraw);

    const int tid  = threadIdx.x;
    const int wid  = tid >> 5;
    const int lane = tid & 31;
    const int wm   = wid & 3;
    const int wn   = wid >> 2;
    const int m0   = blockIdx.y * 128;
    const int n0   = blockIdx.x * 128;

    const float* Ag = A  + (size_t)m0 * K;
    const float* Bg = BT + (size_t)n0 * K;
    const int NK = K / 32;

    float4 stA[4], stB[4];

    auto ldg_tile = [&](int kt) {
        #pragma unroll
        for (int j = 0; j < 4; j++) {
            int idx = tid + j * 256;
            int r = idx >> 3, c4 = idx & 7;
            stA[j] = *(const float4*)(Ag + (size_t)r * K + kt * 32 + c4 * 4);
            stB[j] = *(const float4*)(Bg + (size_t)r * K + kt * 32 + c4 * 4);
        }
    };
    auto sts_tile = [&](int bf) {
        char* buf = smraw + bf * GBUF;
        #pragma unroll
        for (int j = 0; j < 4; j++) {
            int idx = tid + j * 256;
            int r = idx >> 3, c4 = idx & 7;
            uint2 hi, lo;
            split_pack(stA[j], hi, lo);
            *(uint2*)(buf + OFF_AHI + r * GP + c4 * 8) = hi;
            *(uint2*)(buf + OFF_ALO + r * GP + c4 * 8) = lo;
            split_pack(stB[j], hi, lo);
            *(uint2*)(buf + OFF_BHI + r * GP + c4 * 8) = hi;
            *(uint2*)(buf + OFF_BLO + r * GP + c4 * 8) = lo;
        }
    };

    float acc[2][8][4];
    #pragma unroll
    for (int i = 0; i < 2; i++)
        #pragma unroll
        for (int j = 0; j < 8; j++)
            #pragma unroll
            for (int k = 0; k < 4; k++) acc[i][j][k] = 0.f;

    const int g   = lane >> 3;
    const int lr  = lane & 7;
    const int rowsel = ((g & 1) << 3) + lr;
    const int kg  = (g >> 1) << 4;

    ldg_tile(0);
    sts_tile(0);
    __syncthreads();

    for (int kt = 0; kt < NK; kt++) {
        if (kt + 1 < NK) ldg_tile(kt + 1);

        const uint32_t bufb = sbase + (kt & 1) * GBUF;
        #pragma unroll
        for (int ks = 0; ks < 2; ks++) {
            const uint32_t koff = ks * 32 + kg;
            uint32_t a_hi[2][4], a_lo[2][4];
            #pragma unroll
            for (int am = 0; am < 2; am++) {
                uint32_t ad = bufb + OFF_AHI + (wm * 32 + am * 16 + rowsel) * GP + koff;
                LDM4(a_hi[am], ad);
                LDM4(a_lo[am], ad + (OFF_ALO - OFF_AHI));
            }
            #pragma unroll
            for (int bp = 0; bp < 4; bp++) {
                uint32_t bd = bufb + OFF_BHI + (wn * 64 + bp * 16 + rowsel) * GP + koff;
                uint32_t bh[4], bl[4];
                LDM4(bh, bd);
                LDM4(bl, bd + (OFF_BLO - OFF_BHI));
                #pragma unroll
                for (int am = 0; am < 2; am++) {
                    #pragma unroll
                    for (int sub = 0; sub < 2; sub++) {
                        float* d = acc[am][bp * 2 + sub];
                        MMA_BF16(d, a_hi[am], bh[sub], bh[2 + sub]);
                        MMA_BF16(d, a_hi[am], bl[sub], bl[2 + sub]);
                        MMA_BF16(d, a_lo[am], bh[sub], bh[2 + sub]);
                    }
                }
            }
        }
        if (kt + 1 < NK) {
            sts_tile((kt + 1) & 1);
            __syncthreads();
        }
    }

    const int rbase = m0 + wm * 32 + (lane >> 2);
    const int cbase = n0 + wn * 64 + (lane & 3) * 2;
    #pragma unroll
    for (int am = 0; am < 2; am++) {
        #pragma unroll
        for (int bn = 0; bn < 8; bn++) {
            int col = cbase + bn * 8;
            float b0 = bias[col], b1 = bias[col + 1];
            int r0 = rbase + am * 16;
            float2 v0 = make_float2(acc[am][bn][0] + b0, acc[am][bn][1] + b1);
            float2 v1 = make_float2(acc[am][bn][2] + b0, acc[am][bn][3] + b1);
            *(float2*)(C + (size_t)r0 * N + col)       = v0;
            *(float2*)(C + (size_t)(r0 + 8) * N + col) = v1;
        }
    }
}

// ---------------------------------------------------------------- scatter K,V
__global__ void scatter_kv(float* __restrict__ present) {
    int idx = blockIdx.x * blockDim.x + threadIdx.x;
    if (idx >= 2 * B_SZ * N_HEADS * S_LEN * HD) return;
    int d = idx & 63;
    int s = (idx >> 6) & (S_LEN - 1);
    int h = (idx >> 17) & (N_HEADS - 1);
    int b = (idx >> 21) & (B_SZ - 1);
    int c = idx >> 22;
    present[idx] = g_qkv[(size_t)(b * S_LEN + s) * N3 + D_MODEL + c * D_MODEL + h * HD + d];
}

// ---------------------------------------------------------------- mma flash attention
// 4 warps, BM=64 q rows (16/warp), BN=64 keys/tile, hd=64.
// S = QK^T and O += P V via m16n8k16 bf16 with hi/lo split (3 MMAs each).
// Softmax in exp2 domain (0.125*log2e folded into Q); exp via FMA-pipe poly.
#define FP       144            // bf16 tile pitch bytes (64*2 + 16 pad)
#define FQHI     0
#define FQLO     9216
#define FKHI     18432
#define FKLO     27648
#define FVHI     36864
#define FVLO     46080
#define F_SMEM   55296

__global__ __launch_bounds__(128) void flash_mma(const float* __restrict__ present) {
    extern __shared__ char sm[];
    const uint32_t sb = smem_u32(sm);
    const int tid  = threadIdx.x;
    const int wid  = tid >> 5;
    const int lane = tid & 31;
    const int b  = blockIdx.y >> 4;
    const int h  = blockIdx.y & 15;
    const int q0 = blockIdx.x * 64;

    const float* Kg = present + ((size_t)(b * N_HEADS + h)) * S_LEN * HD;
    const float* Vg = present + ((size_t)((2 + b) * N_HEADS + h)) * S_LEN * HD;

    // ---- load Q tile, scaled by 0.125 * log2(e)
    {
        const float QS = 0.125f * 1.44269504f;
        int r = tid >> 1, half = tid & 1;
        const float* src = g_qkv + (size_t)(b * S_LEN + q0 + r) * N3 + h * HD + half * 32;
        char* dhi = sm + FQHI + r * FP + half * 64;
        char* dlo = sm + FQLO + r * FP + half * 64;
        #pragma unroll
        for (int j = 0; j < 8; j++) {
            float4 v = *(const float4*)(src + j * 4);
            v.x *= QS; v.y *= QS; v.z *= QS; v.w *= QS;
            uint2 hi, lo; split_pack(v, hi, lo);
            *(uint2*)(dhi + j * 8) = hi;
            *(uint2*)(dlo + j * 8) = lo;
        }
    }
    __syncthreads();

    // ldmatrix lane addressing (same scheme as mma_gemm)
    const int g   = lane >> 3;
    const int lr  = lane & 7;
    const int rowsel = ((g & 1) << 3) + lr;
    const int kg  = (g >> 1) << 4;

    // cache Q A-fragments (Q smem never overwritten)
    uint32_t qh[4][4], ql[4][4];
    #pragma unroll
    for (int ds = 0; ds < 4; ds++) {
        uint32_t ad = sb + FQHI + (wid * 16 + rowsel) * FP + ds * 32 + kg;
        LDM4(qh[ds], ad);
        LDM4(ql[ds], ad + (FQLO - FQHI));
    }

    float o[4][2][4];
    #pragma unroll
    for (int i = 0; i < 4; i++)
        #pragma unroll
        for (int j = 0; j < 2; j++)
            #pragma unroll
            for (int k = 0; k < 4; k++) o[i][j][k] = 0.f;
    float m0r = -1e30f, m1r = -1e30f, l0 = 0.f, l1 = 0.f;

    const int nT = blockIdx.x + 1;
    for (int t = 0; t < nT; t++) {
        const int k0 = t * 64;
        __syncthreads();            // everyone done reading prev K/V
        {
            int r = tid >> 1, half = tid & 1;
            const float* ks = Kg + (size_t)(k0 + r) * HD + half * 32;
            const float* vs = Vg + (size_t)(k0 + r) * HD + half * 32;
            uint32_t off = r * FP + half * 64;
            #pragma unroll
            for (int j = 0; j < 8; j++) {
                float4 kv = *(const float4*)(ks + j * 4);
                uint2 hi, lo; split_pack(kv, hi, lo);
                *(uint2*)(sm + FKHI + off + j * 8) = hi;
                *(uint2*)(sm + FKLO + off + j * 8) = lo;
                float4 vv = *(const float4*)(vs + j * 4);
                split_pack(vv, hi, lo);
                *(uint2*)(sm + FVHI + off + j * 8) = hi;
                *(uint2*)(sm + FVLO + off + j * 8) = lo;
            }
        }
        __syncthreads();

        // ---- S = Q K^T   s[nt][sub][4]
        float s[4][2][4];
        #pragma unroll
        for (int i = 0; i < 4; i++)
            #pragma unroll
            for (int j = 0; j < 2; j++)
                #pragma unroll
                for (int k = 0; k < 4; k++) s[i][j][k] = 0.f;

        #pragma unroll
        for (int nt = 0; nt < 4; nt++) {
            #pragma unroll
            for (int ds = 0; ds < 4; ds++) {
                uint32_t bd = sb + FKHI + (nt * 16 + rowsel) * FP + ds * 32 + kg;
                uint32_t bh[4], bl[4];
                LDM4(bh, bd);
                LDM4(bl, bd + (FKLO - FKHI));
                #pragma unroll
                for (int sub = 0; sub < 2; sub++) {
                    float* d = s[nt][sub];
                    MMA_BF16(d, qh[ds], bh[sub], bh[2 + sub]);
                    MMA_BF16(d, qh[ds], bl[sub], bl[2 + sub]);
                    MMA_BF16(d, ql[ds], bh[sub], bh[2 + sub]);
                }
            }
        }

        // ---- causal mask (diagonal tile only; k0 == q0 there)
        if (t == nT - 1) {
            const int row0 = q0 + wid * 16 + (lane >> 2);
            #pragma unroll
            for (int nt = 0; nt < 4; nt++)
                #pragma unroll
                for (int sub = 0; sub < 2; sub++) {
                    int colb = k0 + nt * 16 + sub * 8 + (lane & 3) * 2;
                    if (colb     > row0)     s[nt][sub][0] = -1e30f;
                    if (colb + 1 > row0)     s[nt][sub][1] = -1e30f;
                    if (colb     > row0 + 8) s[nt][sub][2] = -1e30f;
                    if (colb + 1 > row0 + 8) s[nt][sub][3] = -1e30f;
                }
        }

        // ---- online softmax (exp2 domain)
        float mx0 = -1e30f, mx1 = -1e30f;
        #pragma unroll
        for (int nt = 0; nt < 4; nt++)
            #pragma unroll
            for (int sub = 0; sub < 2; sub++) {
                mx0 = fmaxf(mx0, fmaxf(s[nt][sub][0], s[nt][sub][1]));
                mx1 = fmaxf(mx1, fmaxf(s[nt][sub][2], s[nt][sub][3]));
            }
        mx0 = fmaxf(mx0, __shfl_xor_sync(0xffffffffu, mx0, 1));
        mx0 = fmaxf(mx0, __shfl_xor_sync(0xffffffffu, mx0, 2));
        mx1 = fmaxf(mx1, __shfl_xor_sync(0xffffffffu, mx1, 1));
        mx1 = fmaxf(mx1, __shfl_xor_sync(0xffffffffu, mx1, 2));
        float nm0 = fmaxf(m0r, mx0), nm1 = fmaxf(m1r, mx1);
        float c0 = exp2_fast(m0r - nm0), c1 = exp2_fast(m1r - nm1);
        m0r = nm0; m1r = nm1;

        float rs0 = 0.f, rs1 = 0.f;
        uint32_t pa_hi[4][4], pa_lo[4][4];
        #pragma unroll
        for (int kc = 0; kc < 4; kc++) {
            #pragma unroll
            for (int sub = 0; sub < 2; sub++) {
                float p0 = exp2_fast(s[kc][sub][0] - nm0);
                float p1 = exp2_fast(s[kc][sub][1] - nm0);
                float p2 = exp2_fast(s[kc][sub][2] - nm1);
                float p3 = exp2_fast(s[kc][sub][3] - nm1);
                rs0 += p0 + p1;
                rs1 += p2 + p3;
                float h0 = __bfloat162float(__float2bfloat16(p0));
                float h1 = __bfloat162float(__float2bfloat16(p1));
                float h2 = __bfloat162float(__float2bfloat16(p2));
                float h3 = __bfloat162float(__float2bfloat16(p3));
                pa_hi[kc][sub * 2 + 0] = pack2bf(h0, h1);
                pa_hi[kc][sub * 2 + 1] = pack2bf(h2, h3);
                pa_lo[kc][sub * 2 + 0] = pack2bf(p0 - h0, p1 - h1);
                pa_lo[kc][sub * 2 + 1] = pack2bf(p2 - h2, p3 - h3);
            }
        }
        rs0 += __shfl_xor_sync(0xffffffffu, rs0, 1);
        rs0 += __shfl_xor_sync(0xffffffffu, rs0, 2);
        rs1 += __shfl_xor_sync(0xffffffffu, rs1, 1);
        rs1 += __shfl_xor_sync(0xffffffffu, rs1, 2);
        l0 = l0 * c0 + rs0;
        l1 = l1 * c1 + rs1;

        // rescale O
        #pragma unroll
        for (int dt = 0; dt < 4; dt++)
            #pragma unroll
            for (int sub = 0; sub < 2; sub++) {
                o[dt][sub][0] *= c0; o[dt][sub][1] *= c0;
                o[dt][sub][2] *= c1; o[dt][sub][3] *= c1;
            }

        // ---- O += P V    (V via ldmatrix.trans: B frags b0=r[2s], b1=r[2s+1])
        const uint32_t vlanebase = (lane & 15) * FP + ((lane >> 4) << 4);
        #pragma unroll
        for (int kc = 0; kc < 4; kc++) {
            #pragma unroll
            for (int dt = 0; dt < 4; dt++) {
                uint32_t va = sb + FVHI + kc * 16 * FP + dt * 32 + vlanebase;
                uint32_t vh[4], vl[4];
                LDM4T(vh, va);
                LDM4T(vl, va + (FVLO - FVHI));
                #pragma unroll
                for (int sub = 0; sub < 2; sub++) {
                    float* d = o[dt][sub];
                    MMA_BF16(d, pa_hi[kc], vh[2 * sub], vh[2 * sub + 1]);
                    MMA_BF16(d, pa_hi[kc], vl[2 * sub], vl[2 * sub + 1]);
                    MMA_BF16(d, pa_lo[kc], vh[2 * sub], vh[2 * sub + 1]);
                }
            }
        }
    }

    // ---- write O / l
    const float inv0 = 1.0f / l0, inv1 = 1.0f / l1;
    const int row0 = q0 + wid * 16 + (lane >> 2);
    float* obase = g_attn + (size_t)(b * S_LEN) * D_MODEL + h * HD + (lane & 3) * 2;
    #pragma unroll
    for (int dt = 0; dt < 4; dt++)
        #pragma unroll
        for (int sub = 0; sub < 2; sub++) {
            int d = dt * 16 + sub * 8;
            float2 v0 = make_float2(o[dt][sub][0] * inv0, o[dt][sub][1] * inv0);
            float2 v1 = make_float2(o[dt][sub][2] * inv1, o[dt][sub][3] * inv1);
            *(float2*)(obase + (size_t)row0 * D_MODEL + d)       = v0;
            *(float2*)(obase + (size_t)(row0 + 8) * D_MODEL + d) = v1;
        }
}

// ---------------------------------------------------------------- launcher
extern "C" void kernel_launch(void* const* d_in, const int* in_sizes, int n_in,
                              void* d_out, int out_size) {
    const float* x        = (const float*)d_in[0];
    const float* c_attn_w = (const float*)d_in[1];
    const float* c_attn_b = (const float*)d_in[2];
    const float* c_proj_w = (const float*)d_in[3];
    const float* c_proj_b = (const float*)d_in[4];
    const float* q_a1     = (const float*)d_in[5];
    const float* q_a2     = (const float*)d_in[6];
    const float* v_a1     = (const float*)d_in[7];
    const float* v_a2     = (const float*)d_in[8];

    float* out     = (float*)d_out;
    float* a_out   = out;
    float* present = out + (size_t)ROWS * D_MODEL;

    float *weffT, *projT, *qkv, *attn;
    cudaGetSymbolAddress((void**)&weffT, g_weffT);
    cudaGetSymbolAddress((void**)&projT, g_projT);
    cudaGetSymbolAddress((void**)&qkv,   g_qkv);
    cudaGetSymbolAddress((void**)&attn,  g_attn);

    cudaFuncSetAttribute(mma_gemm, cudaFuncAttributeMaxDynamicSharedMemorySize, G_SMEM);
    cudaFuncSetAttribute(flash_mma, cudaFuncAttributeMaxDynamicSharedMemorySize, F_SMEM);

    // 1) transposed effective weights
    build_weffT<<<dim3(N3 / 32, D_MODEL / 32), dim3(32, 32)>>>(c_attn_w, q_a1, q_a2, v_a1, v_a2);
    build_projT<<<dim3(D_MODEL / 32, D_MODEL / 32), dim3(32, 32)>>>(c_proj_w);

    // 2) qkv = x @ W_eff + b
    mma_gemm<<<dim3(N3 / 128, ROWS / 128), 256, G_SMEM>>>(
        N3, D_MODEL, x, weffT, c_attn_b, qkv);

    // 3) present
    scatter_kv<<<(2 * ROWS * D_MODEL + 255) / 256, 256>>>(present);

    // 4) attention (tensor-core flash)
    flash_mma<<<dim3(S_LEN / 64, B_SZ * N_HEADS), 128, F_SMEM>>>(present);

    // 5) a = attn @ c_proj_w + b
    mma_gemm<<<dim3(D_MODEL / 128, ROWS / 128), 256, G_SMEM>>>(
        D_MODEL, D_MODEL, attn, projT, c_proj_b, a_out);
}

// round 5
// speedup vs baseline: 2.5138x; 1.2753x over previous
#include <cuda_runtime.h>
#include <cuda_bf16.h>
#include <cstdint>

// ---------------------------------------------------------------- constants
#define B_SZ    2
#define S_LEN   2048
#define D_MODEL 1024
#define N_HEADS 16
#define HD      64
#define N3      (3 * D_MODEL)
#define ROWS    (B_SZ * S_LEN)
#define LORA_SCALE 0.5f
#define QSCALE  0.18033688011112042f   // 0.125 * log2(e)

// ---------------------------------------------------------------- scratch (bf16 hi/lo pairs)
__device__ __nv_bfloat16 g_wT_hi[(size_t)N3 * D_MODEL];
__device__ __nv_bfloat16 g_wT_lo[(size_t)N3 * D_MODEL];
__device__ __nv_bfloat16 g_pT_hi[(size_t)D_MODEL * D_MODEL];
__device__ __nv_bfloat16 g_pT_lo[(size_t)D_MODEL * D_MODEL];
__device__ __nv_bfloat16 g_x_hi[(size_t)ROWS * D_MODEL];
__device__ __nv_bfloat16 g_x_lo[(size_t)ROWS * D_MODEL];
__device__ __nv_bfloat16 g_q_hi[(size_t)ROWS * D_MODEL];
__device__ __nv_bfloat16 g_q_lo[(size_t)ROWS * D_MODEL];
__device__ __nv_bfloat16 g_kv_hi[(size_t)4 * N_HEADS * S_LEN * HD];  // [c,b,h,s,d]
__device__ __nv_bfloat16 g_kv_lo[(size_t)4 * N_HEADS * S_LEN * HD];
__device__ __nv_bfloat16 g_o_hi[(size_t)ROWS * D_MODEL];
__device__ __nv_bfloat16 g_o_lo[(size_t)ROWS * D_MODEL];

// ---------------------------------------------------------------- helpers
__device__ __forceinline__ uint32_t smem_u32(const void* p) {
    uint32_t a;
    asm("{ .reg .u64 t; cvta.to.shared.u64 t, %1; cvt.u32.u64 %0, t; }" : "=r"(a) : "l"(p));
    return a;
}
__device__ __forceinline__ void cp16(uint32_t saddr, const void* gptr) {
    asm volatile("cp.async.cg.shared.global [%0], [%1], 16;"
                 :: "r"(saddr), "l"(__cvta_generic_to_global(gptr)) : "memory");
}
#define CP_COMMIT() asm volatile("cp.async.commit_group;" ::: "memory")
#define CP_WAIT(N)  asm volatile("cp.async.wait_group " #N ";" ::: "memory")

#define LDM4(r, addr)                                                        \
    asm volatile("ldmatrix.sync.aligned.m8n8.x4.shared.b16 {%0,%1,%2,%3}, [%4];" \
        : "=r"((r)[0]), "=r"((r)[1]), "=r"((r)[2]), "=r"((r)[3]) : "r"(addr))
#define LDM4T(r, addr)                                                       \
    asm volatile("ldmatrix.sync.aligned.m8n8.x4.trans.shared.b16 {%0,%1,%2,%3}, [%4];" \
        : "=r"((r)[0]), "=r"((r)[1]), "=r"((r)[2]), "=r"((r)[3]) : "r"(addr))
#define MMA_BF16(d, a, b0, b1)                                               \
    asm volatile("mma.sync.aligned.m16n8k16.row.col.f32.bf16.bf16.f32 "      \
        "{%0,%1,%2,%3}, {%4,%5,%6,%7}, {%8,%9}, {%0,%1,%2,%3};"              \
        : "+f"((d)[0]), "+f"((d)[1]), "+f"((d)[2]), "+f"((d)[3])             \
        : "r"((a)[0]), "r"((a)[1]), "r"((a)[2]), "r"((a)[3]),                \
          "r"(b0), "r"(b1))

__device__ __forceinline__ uint32_t pack2bf(float a, float b) {
    return ((uint32_t)__bfloat16_as_ushort(__float2bfloat16(b)) << 16) |
           __bfloat16_as_ushort(__float2bfloat16(a));
}
// split pair (a,b) -> packed hi u32, packed lo u32
__device__ __forceinline__ uint32_t split2(float a, float b, uint32_t& lo) {
    __nv_bfloat16 ha = __float2bfloat16(a), hb = __float2bfloat16(b);
    lo = pack2bf(a - __bfloat162float(ha), b - __bfloat162float(hb));
    return ((uint32_t)__bfloat16_as_ushort(hb) << 16) | __bfloat16_as_ushort(ha);
}
__device__ __forceinline__ void split_pack(float4 v, uint2& hi, uint2& lo) {
    uint32_t l0, l1;
    hi.x = split2(v.x, v.y, l0);
    hi.y = split2(v.z, v.w, l1);
    lo.x = l0; lo.y = l1;
}

// fast 2^t for t <= 0, FMA-pipe only. rel err ~2.4e-6.
__device__ __forceinline__ float exp2_fast(float t) {
    t = fmaxf(t, -126.0f);
    float r = t + 12582912.0f;
    float f = t - (r - 12582912.0f);
    int n_i = __float_as_int(r) - 0x4B400000;
    float p = 1.3333558e-3f;
    p = fmaf(p, f, 9.6181291e-3f);
    p = fmaf(p, f, 5.5504109e-2f);
    p = fmaf(p, f, 2.4022651e-1f);
    p = fmaf(p, f, 6.9314718e-1f);
    p = fmaf(p, f, 1.0f);
    return p * __int_as_float((n_i + 127) << 23);
}

// ---------------------------------------------------------------- weight prep
__global__ __launch_bounds__(1024) void build_weffT_hl(
    const float* __restrict__ w,
    const float* __restrict__ qa1, const float* __restrict__ qa2,
    const float* __restrict__ va1, const float* __restrict__ va2) {
    __shared__ float t[32][33];
    int tx = threadIdx.x, ty = threadIdx.y;
    int n0 = blockIdx.x * 32, d0 = blockIdx.y * 32;
    int d = d0 + ty, n = n0 + tx;
    float val = w[(size_t)d * N3 + n];
    if (n < D_MODEL) {
        float s = 0.f;
        #pragma unroll
        for (int r = 0; r < 16; r++) s += qa1[d * 16 + r] * qa2[r * D_MODEL + n];
        val += LORA_SCALE * s;
    } else if (n >= 2 * D_MODEL) {
        int nn = n - 2 * D_MODEL;
        float s = 0.f;
        #pragma unroll
        for (int r = 0; r < 16; r++) s += va1[d * 16 + r] * va2[r * D_MODEL + nn];
        val += LORA_SCALE * s;
    }
    t[ty][tx] = val;
    __syncthreads();
    float v = t[tx][ty];
    __nv_bfloat16 hi = __float2bfloat16(v);
    size_t idx = (size_t)(n0 + ty) * D_MODEL + d0 + tx;
    g_wT_hi[idx] = hi;
    g_wT_lo[idx] = __float2bfloat16(v - __bfloat162float(hi));
}

__global__ __launch_bounds__(1024) void build_projT_hl(const float* __restrict__ w) {
    __shared__ float t[32][33];
    int tx = threadIdx.x, ty = threadIdx.y;
    int n0 = blockIdx.x * 32, d0 = blockIdx.y * 32;
    t[ty][tx] = w[(size_t)(d0 + ty) * D_MODEL + n0 + tx];
    __syncthreads();
    float v = t[tx][ty];
    __nv_bfloat16 hi = __float2bfloat16(v);
    size_t idx = (size_t)(n0 + ty) * D_MODEL + d0 + tx;
    g_pT_hi[idx] = hi;
    g_pT_lo[idx] = __float2bfloat16(v - __bfloat162float(hi));
}

__global__ void split_x(const float* __restrict__ x) {
    size_t i = (size_t)blockIdx.x * blockDim.x + threadIdx.x;
    if (i >= (size_t)ROWS * D_MODEL / 4) return;
    float4 v = *(const float4*)(x + i * 4);
    uint2 hi, lo;
    split_pack(v, hi, lo);
    *(uint2*)(g_x_hi + i * 4) = hi;
    *(uint2*)(g_x_lo + i * 4) = lo;
}

// ---------------------------------------------------------------- mma GEMM (bf16 hi/lo inputs, cp.async)
// MODE 0: C = A@B^T + bias (fp32 out)
// MODE 1: qkv epilogue: q -> g_q_hi/lo (scaled), k/v -> present fp32 + g_kv_hi/lo
#define GP          80
#define OFF_AHI     0
#define OFF_ALO     10240
#define OFF_BHI     20480
#define OFF_BLO     30720
#define GBUF        40960
#define G_SMEM      (2 * GBUF)

template<int MODE>
__global__ __launch_bounds__(256, 2) void mma_gemm_bf(
    int N, int K,
    const __nv_bfloat16* __restrict__ Ahi, const __nv_bfloat16* __restrict__ Alo,
    const __nv_bfloat16* __restrict__ Bhi, const __nv_bfloat16* __restrict__ Blo,
    const float* __restrict__ bias, float* __restrict__ C,
    float* __restrict__ present) {
    extern __shared__ char smraw[];
    const uint32_t sbase = smem_u32(smraw);

    const int tid  = threadIdx.x;
    const int wid  = tid >> 5;
    const int lane = tid & 31;
    const int wm   = wid & 3;
    const int wn   = wid >> 2;
    const int m0   = blockIdx.y * 128;
    const int n0   = blockIdx.x * 128;
    const int NK   = K / 32;

    auto load_stage = [&](int kt, int bf) {
        const uint32_t sb0 = sbase + bf * GBUF;
        #pragma unroll
        for (int j = 0; j < 8; j++) {
            int c   = tid + j * 256;
            int arr = j >> 1;                 // 0 Ahi, 1 Alo, 2 Bhi, 3 Blo
            int rem = c & 511;
            int r   = rem >> 2, p = rem & 3;
            uint32_t sa = sb0 + arr * 10240 + r * GP + p * 16;
            const __nv_bfloat16* gb;
            if      (arr == 0) gb = Ahi + (size_t)(m0 + r) * K;
            else if (arr == 1) gb = Alo + (size_t)(m0 + r) * K;
            else if (arr == 2) gb = Bhi + (size_t)(n0 + r) * K;
            else               gb = Blo + (size_t)(n0 + r) * K;
            cp16(sa, (const char*)gb + kt * 64 + p * 16);
        }
    };

    float acc[2][8][4];
    #pragma unroll
    for (int i = 0; i < 2; i++)
        #pragma unroll
        for (int j = 0; j < 8; j++)
            #pragma unroll
            for (int k = 0; k < 4; k++) acc[i][j][k] = 0.f;

    const int g   = lane >> 3;
    const int lr  = lane & 7;
    const int rowsel = ((g & 1) << 3) + lr;
    const int kg  = (g >> 1) << 4;

    load_stage(0, 0);
    CP_COMMIT();

    for (int kt = 0; kt < NK; kt++) {
        if (kt + 1 < NK) {
            load_stage(kt + 1, (kt + 1) & 1);
            CP_COMMIT();
            CP_WAIT(1);
        } else {
            CP_WAIT(0);
        }
        __syncthreads();

        const uint32_t bufb = sbase + (kt & 1) * GBUF;
        #pragma unroll
        for (int ks = 0; ks < 2; ks++) {
            const uint32_t koff = ks * 32 + kg;
            uint32_t a_hi[2][4], a_lo[2][4];
            #pragma unroll
            for (int am = 0; am < 2; am++) {
                uint32_t ad = bufb + OFF_AHI + (wm * 32 + am * 16 + rowsel) * GP + koff;
                LDM4(a_hi[am], ad);
                LDM4(a_lo[am], ad + (OFF_ALO - OFF_AHI));
            }
            #pragma unroll
            for (int bp = 0; bp < 4; bp++) {
                uint32_t bd = bufb + OFF_BHI + (wn * 64 + bp * 16 + rowsel) * GP + koff;
                uint32_t bh[4], bl[4];
                LDM4(bh, bd);
                LDM4(bl, bd + (OFF_BLO - OFF_BHI));
                #pragma unroll
                for (int am = 0; am < 2; am++) {
                    #pragma unroll
                    for (int sub = 0; sub < 2; sub++) {
                        float* d = acc[am][bp * 2 + sub];
                        MMA_BF16(d, a_hi[am], bh[sub], bh[2 + sub]);
                        MMA_BF16(d, a_hi[am], bl[sub], bl[2 + sub]);
                        MMA_BF16(d, a_lo[am], bh[sub], bh[2 + sub]);
                    }
                }
            }
        }
        __syncthreads();
    }

    const int rbase = m0 + wm * 32 + (lane >> 2);
    const int cbase = n0 + wn * 64 + (lane & 3) * 2;

    if (MODE == 0) {
        #pragma unroll
        for (int am = 0; am < 2; am++) {
            #pragma unroll
            for (int bn = 0; bn < 8; bn++) {
                int col = cbase + bn * 8;
                float b0 = bias[col], b1 = bias[col + 1];
                int r0 = rbase + am * 16;
                float2 v0 = make_float2(acc[am][bn][0] + b0, acc[am][bn][1] + b1);
                float2 v1 = make_float2(acc[am][bn][2] + b0, acc[am][bn][3] + b1);
                *(float2*)(C + (size_t)r0 * N + col)       = v0;
                *(float2*)(C + (size_t)(r0 + 8) * N + col) = v1;
            }
        }
    } else {
        if (blockIdx.x < 8) {
            // q: scale by QSCALE, write bf16 hi/lo
            #pragma unroll
            for (int am = 0; am < 2; am++) {
                #pragma unroll
                for (int bn = 0; bn < 8; bn++) {
                    int col = cbase + bn * 8;
                    float b0 = bias[col], b1 = bias[col + 1];
                    int r0 = rbase + am * 16;
                    float y00 = (acc[am][bn][0] + b0) * QSCALE;
                    float y01 = (acc[am][bn][1] + b1) * QSCALE;
                    float y10 = (acc[am][bn][2] + b0) * QSCALE;
                    float y11 = (acc[am][bn][3] + b1) * QSCALE;
                    uint32_t lo0, lo1;
                    uint32_t hi0 = split2(y00, y01, lo0);
                    uint32_t hi1 = split2(y10, y11, lo1);
                    size_t i0 = (size_t)r0 * D_MODEL + col;
                    size_t i1 = (size_t)(r0 + 8) * D_MODEL + col;
                    *(uint32_t*)(g_q_hi + i0) = hi0;
                    *(uint32_t*)(g_q_lo + i0) = lo0;
                    *(uint32_t*)(g_q_hi + i1) = hi1;
                    *(uint32_t*)(g_q_lo + i1) = lo1;
                }
            }
        } else {
            // k/v: fp32 -> present, bf16 hi/lo -> g_kv
            const int cc = (blockIdx.x >= 16) ? 1 : 0;
            const int bb = m0 >> 11;
            const size_t cb_off = (size_t)((cc * 2 + bb) * 16) * 131072;
            #pragma unroll
            for (int am = 0; am < 2; am++) {
                #pragma unroll
                for (int bn = 0; bn < 8; bn++) {
                    int col = cbase + bn * 8;
                    int nn  = col - D_MODEL - cc * D_MODEL;
                    int h   = nn >> 6, d = nn & 63;
                    float b0 = bias[col], b1 = bias[col + 1];
                    int r0 = rbase + am * 16;
                    int s0 = r0 & 2047;
                    float y00 = acc[am][bn][0] + b0;
                    float y01 = acc[am][bn][1] + b1;
                    float y10 = acc[am][bn][2] + b0;
                    float y11 = acc[am][bn][3] + b1;
                    size_t i0 = cb_off + (size_t)h * 131072 + (size_t)s0 * 64 + d;
                    size_t i1 = i0 + 8 * 64;
                    *(float2*)(present + i0) = make_float2(y00, y01);
                    *(float2*)(present + i1) = make_float2(y10, y11);
                    uint32_t lo0, lo1;
                    uint32_t hi0 = split2(y00, y01, lo0);
                    uint32_t hi1 = split2(y10, y11, lo1);
                    *(uint32_t*)(g_kv_hi + i0) = hi0;
                    *(uint32_t*)(g_kv_lo + i0) = lo0;
                    *(uint32_t*)(g_kv_hi + i1) = hi1;
                    *(uint32_t*)(g_kv_lo + i1) = lo1;
                }
            }
        }
    }
}

// ---------------------------------------------------------------- mma flash attention
// K/V/Q loaded as pre-split bf16 via cp.async; O written as bf16 hi/lo.
#define FP       144
#define FSTAGE   36864          // K_hi | K_lo | V_hi | V_lo, each 64*144
#define FKHI     0
#define FKLO     9216
#define FVHI     18432
#define FVLO     27648
#define FQHI     73728
#define FQLO     82944
#define F_SMEM   92160

__global__ __launch_bounds__(128) void flash_mma() {
    extern __shared__ char sm[];
    const uint32_t sb = smem_u32(sm);
    const int tid  = threadIdx.x;
    const int wid  = tid >> 5;
    const int lane = tid & 31;
    const int b  = blockIdx.y >> 4;
    const int h  = blockIdx.y & 15;
    const int q0 = blockIdx.x * 64;

    const size_t kbase = (size_t)(b * 16 + h) * 131072;
    const size_t vbase = (size_t)((2 + b) * 16 + h) * 131072;

    // Q tile cp.async (group 0, together with kv stage 0)
    {
        #pragma unroll
        for (int j = 0; j < 8; j++) {
            int c = tid + j * 128;
            int arr = j >> 2;                  // 0 hi, 1 lo
            int rem = c & 511;
            int r = rem >> 3, p = rem & 7;
            uint32_t sa = sb + FQHI + arr * 9216 + r * FP + p * 16;
            const __nv_bfloat16* src = (arr ? g_q_lo : g_q_hi)
                + (size_t)(b * S_LEN + q0 + r) * D_MODEL + h * HD;
            cp16(sa, (const char*)src + p * 16);
        }
    }

    auto load_kv = [&](int t, int bf) {
        const uint32_t s0 = sb + bf * FSTAGE;
        const int k0 = t * 64;
        #pragma unroll
        for (int j = 0; j < 16; j++) {
            int c = tid + j * 128;
            int arr = j >> 2;                  // 0 Khi, 1 Klo, 2 Vhi, 3 Vlo
            int rem = c & 511;
            int r = rem >> 3, p = rem & 7;
            uint32_t sa = s0 + arr * 9216 + r * FP + p * 16;
            const __nv_bfloat16* gb;
            if      (arr == 0) gb = g_kv_hi + kbase;
            else if (arr == 1) gb = g_kv_lo + kbase;
            else if (arr == 2) gb = g_kv_hi + vbase;
            else               gb = g_kv_lo + vbase;
            cp16(sa, (const char*)gb + (size_t)(k0 + r) * 128 + p * 16);
        }
    };

    load_kv(0, 0);
    CP_COMMIT();

    const int g   = lane >> 3;
    const int lr  = lane & 7;
    const int rowsel = ((g & 1) << 3) + lr;
    const int kg  = (g >> 1) << 4;
    const uint32_t vlanebase = (lane & 15) * FP + ((lane >> 4) << 4);

    uint32_t qh[4][4], ql[4][4];
    float o[4][2][4];
    #pragma unroll
    for (int i = 0; i < 4; i++)
        #pragma unroll
        for (int j = 0; j < 2; j++)
            #pragma unroll
            for (int k = 0; k < 4; k++) o[i][j][k] = 0.f;
    float m0r = -1e30f, m1r = -1e30f, l0 = 0.f, l1 = 0.f;

    const int nT = blockIdx.x + 1;
    for (int t = 0; t < nT; t++) {
        if (t + 1 < nT) {
            load_kv(t + 1, (t + 1) & 1);
            CP_COMMIT();
            CP_WAIT(1);
        } else {
            CP_WAIT(0);
        }
        __syncthreads();

        if (t == 0) {
            #pragma unroll
            for (int ds = 0; ds < 4; ds++) {
                uint32_t ad = sb + FQHI + (wid * 16 + rowsel) * FP + ds * 32 + kg;
                LDM4(qh[ds], ad);
                LDM4(ql[ds], ad + (FQLO - FQHI));
            }
        }

        const uint32_t st = sb + (t & 1) * FSTAGE;
        const int k0 = t * 64;

        // ---- S = Q K^T
        float s[4][2][4];
        #pragma unroll
        for (int i = 0; i < 4; i++)
            #pragma unroll
            for (int j = 0; j < 2; j++)
                #pragma unroll
                for (int k = 0; k < 4; k++) s[i][j][k] = 0.f;

        #pragma unroll
        for (int nt = 0; nt < 4; nt++) {
            #pragma unroll
            for (int ds = 0; ds < 4; ds++) {
                uint32_t bd = st + FKHI + (nt * 16 + rowsel) * FP + ds * 32 + kg;
                uint32_t bh[4], bl[4];
                LDM4(bh, bd);
                LDM4(bl, bd + (FKLO - FKHI));
                #pragma unroll
                for (int sub = 0; sub < 2; sub++) {
                    float* d = s[nt][sub];
                    MMA_BF16(d, qh[ds], bh[sub], bh[2 + sub]);
                    MMA_BF16(d, qh[ds], bl[sub], bl[2 + sub]);
                    MMA_BF16(d, ql[ds], bh[sub], bh[2 + sub]);
                }
            }
        }

        // ---- causal mask (diagonal tile only)
        if (t == nT - 1) {
            const int row0 = q0 + wid * 16 + (lane >> 2);
            #pragma unroll
            for (int nt = 0; nt < 4; nt++)
                #pragma unroll
                for (int sub = 0; sub < 2; sub++) {
                    int colb = k0 + nt * 16 + sub * 8 + (lane & 3) * 2;
                    if (colb     > row0)     s[nt][sub][0] = -1e30f;
                    if (colb + 1 > row0)     s[nt][sub][1] = -1e30f;
                    if (colb     > row0 + 8) s[nt][sub][2] = -1e30f;
                    if (colb + 1 > row0 + 8) s[nt][sub][3] = -1e30f;
                }
        }

        // ---- online softmax (exp2 domain)
        float mx0 = -1e30f, mx1 = -1e30f;
        #pragma unroll
        for (int nt = 0; nt < 4; nt++)
            #pragma unroll
            for (int sub = 0; sub < 2; sub++) {
                mx0 = fmaxf(mx0, fmaxf(s[nt][sub][0], s[nt][sub][1]));
                mx1 = fmaxf(mx1, fmaxf(s[nt][sub][2], s[nt][sub][3]));
            }
        mx0 = fmaxf(mx0, __shfl_xor_sync(0xffffffffu, mx0, 1));
        mx0 = fmaxf(mx0, __shfl_xor_sync(0xffffffffu, mx0, 2));
        mx1 = fmaxf(mx1, __shfl_xor_sync(0xffffffffu, mx1, 1));
        mx1 = fmaxf(mx1, __shfl_xor_sync(0xffffffffu, mx1, 2));
        float nm0 = fmaxf(m0r, mx0), nm1 = fmaxf(m1r, mx1);
        float c0 = exp2_fast(m0r - nm0), c1 = exp2_fast(m1r - nm1);
        m0r = nm0; m1r = nm1;

        float rs0 = 0.f, rs1 = 0.f;
        uint32_t pa_hi[4][4], pa_lo[4][4];
        #pragma unroll
        for (int kc = 0; kc < 4; kc++) {
            #pragma unroll
            for (int sub = 0; sub < 2; sub++) {
                float p0 = exp2_fast(s[kc][sub][0] - nm0);
                float p1 = exp2_fast(s[kc][sub][1] - nm0);
                float p2 = exp2_fast(s[kc][sub][2] - nm1);
                float p3 = exp2_fast(s[kc][sub][3] - nm1);
                rs0 += p0 + p1;
                rs1 += p2 + p3;
                uint32_t l01, l23;
                pa_hi[kc][sub * 2 + 0] = split2(p0, p1, l01);
                pa_hi[kc][sub * 2 + 1] = split2(p2, p3, l23);
                pa_lo[kc][sub * 2 + 0] = l01;
                pa_lo[kc][sub * 2 + 1] = l23;
            }
        }
        rs0 += __shfl_xor_sync(0xffffffffu, rs0, 1);
        rs0 += __shfl_xor_sync(0xffffffffu, rs0, 2);
        rs1 += __shfl_xor_sync(0xffffffffu, rs1, 1);
        rs1 += __shfl_xor_sync(0xffffffffu, rs1, 2);
        l0 = l0 * c0 + rs0;
        l1 = l1 * c1 + rs1;

        #pragma unroll
        for (int dt = 0; dt < 4; dt++)
            #pragma unroll
            for (int sub = 0; sub < 2; sub++) {
                o[dt][sub][0] *= c0; o[dt][sub][1] *= c0;
                o[dt][sub][2] *= c1; o[dt][sub][3] *= c1;
            }

        // ---- O += P V
        #pragma unroll
        for (int kc = 0; kc < 4; kc++) {
            #pragma unroll
            for (int dt = 0; dt < 4; dt++) {
                uint32_t va = st + FVHI + kc * 16 * FP + dt * 32 + vlanebase;
                uint32_t vh[4], vl[4];
                LDM4T(vh, va);
                LDM4T(vl, va + (FVLO - FVHI));
                #pragma unroll
                for (int sub = 0; sub < 2; sub++) {
                    float* d = o[dt][sub];
                    MMA_BF16(d, pa_hi[kc], vh[2 * sub], vh[2 * sub + 1]);
                    MMA_BF16(d, pa_hi[kc], vl[2 * sub], vl[2 * sub + 1]);
                    MMA_BF16(d, pa_lo[kc], vh[2 * sub], vh[2 * sub + 1]);
                }
            }
        }
        __syncthreads();
    }

    // ---- write O as bf16 hi/lo (GEMM2 operand)
    const float inv0 = 1.0f / l0, inv1 = 1.0f / l1;
    const int row0 = q0 + wid * 16 + (lane >> 2);
    const size_t obase = (size_t)(b * S_LEN) * D_MODEL + h * HD + (lane & 3) * 2;
    #pragma unroll
    for (int dt = 0; dt < 4; dt++)
        #pragma unroll
        for (int sub = 0; sub < 2; sub++) {
            int d = dt * 16 + sub * 8;
            uint32_t lo0, lo1;
            uint32_t hi0 = split2(o[dt][sub][0] * inv0, o[dt][sub][1] * inv0, lo0);
            uint32_t hi1 = split2(o[dt][sub][2] * inv1, o[dt][sub][3] * inv1, lo1);
            size_t i0 = obase + (size_t)row0 * D_MODEL + d;
            size_t i1 = obase + (size_t)(row0 + 8) * D_MODEL + d;
            *(uint32_t*)(g_o_hi + i0) = hi0;
            *(uint32_t*)(g_o_lo + i0) = lo0;
            *(uint32_t*)(g_o_hi + i1) = hi1;
            *(uint32_t*)(g_o_lo + i1) = lo1;
        }
}

// ---------------------------------------------------------------- launcher
extern "C" void kernel_launch(void* const* d_in, const int* in_sizes, int n_in,
                              void* d_out, int out_size) {
    const float* x        = (const float*)d_in[0];
    const float* c_attn_w = (const float*)d_in[1];
    const float* c_attn_b = (const float*)d_in[2];
    const float* c_proj_w = (const float*)d_in[3];
    const float* c_proj_b = (const float*)d_in[4];
    const float* q_a1     = (const float*)d_in[5];
    const float* q_a2     = (const float*)d_in[6];
    const float* v_a1     = (const float*)d_in[7];
    const float* v_a2     = (const float*)d_in[8];

    float* out     = (float*)d_out;
    float* a_out   = out;
    float* present = out + (size_t)ROWS * D_MODEL;

    __nv_bfloat16 *xhi, *xlo, *whi, *wlo, *phi, *plo, *ohi, *olo;
    cudaGetSymbolAddress((void**)&xhi, g_x_hi);
    cudaGetSymbolAddress((void**)&xlo, g_x_lo);
    cudaGetSymbolAddress((void**)&whi, g_wT_hi);
    cudaGetSymbolAddress((void**)&wlo, g_wT_lo);
    cudaGetSymbolAddress((void**)&phi, g_pT_hi);
    cudaGetSymbolAddress((void**)&plo, g_pT_lo);
    cudaGetSymbolAddress((void**)&ohi, g_o_hi);
    cudaGetSymbolAddress((void**)&olo, g_o_lo);

    cudaFuncSetAttribute(mma_gemm_bf<0>, cudaFuncAttributeMaxDynamicSharedMemorySize, G_SMEM);
    cudaFuncSetAttribute(mma_gemm_bf<1>, cudaFuncAttributeMaxDynamicSharedMemorySize, G_SMEM);
    cudaFuncSetAttribute(flash_mma, cudaFuncAttributeMaxDynamicSharedMemorySize, F_SMEM);

    // 1) operand prep
    build_weffT_hl<<<dim3(N3 / 32, D_MODEL / 32), dim3(32, 32)>>>(c_attn_w, q_a1, q_a2, v_a1, v_a2);
    build_projT_hl<<<dim3(D_MODEL / 32, D_MODEL / 32), dim3(32, 32)>>>(c_proj_w);
    split_x<<<(ROWS * D_MODEL / 4 + 255) / 256, 256>>>(x);

    // 2) qkv GEMM + fused scatter/split epilogue
    mma_gemm_bf<1><<<dim3(N3 / 128, ROWS / 128), 256, G_SMEM>>>(
        N3, D_MODEL, xhi, xlo, whi, wlo, c_attn_b, nullptr, present);

    // 3) attention
    flash_mma<<<dim3(S_LEN / 64, B_SZ * N_HEADS), 128, F_SMEM>>>();

    // 4) output projection
    mma_gemm_bf<0><<<dim3(D_MODEL / 128, ROWS / 128), 256, G_SMEM>>>(
        D_MODEL, D_MODEL, ohi, olo, phi, plo, c_proj_b, a_out, nullptr);
}

// round 6
// speedup vs baseline: 3.3386x; 1.3281x over previous
#include <cuda_runtime.h>
#include <cuda_fp16.h>
#include <cstdint>

// ---------------------------------------------------------------- constants
#define B_SZ    2
#define S_LEN   2048
#define D_MODEL 1024
#define N_HEADS 16
#define HD      64
#define N3      (3 * D_MODEL)
#define ROWS    (B_SZ * S_LEN)
#define LORA_SCALE 0.5f
#define QSCALE  0.18033688011112042f   // 0.125 * log2(e)

// ---------------------------------------------------------------- scratch
__device__ __half g_wT_hi[(size_t)N3 * D_MODEL];
__device__ __half g_wT_lo[(size_t)N3 * D_MODEL];
__device__ __half g_pT_hi[(size_t)D_MODEL * D_MODEL];
__device__ __half g_pT_lo[(size_t)D_MODEL * D_MODEL];
__device__ __half g_x_h[(size_t)ROWS * D_MODEL];               // single fp16
__device__ __half g_q_hi[(size_t)ROWS * D_MODEL];              // Q split (3-term S)
__device__ __half g_q_lo[(size_t)ROWS * D_MODEL];
__device__ __half g_kv_hi[(size_t)4 * N_HEADS * S_LEN * HD];   // [c,b,h,s,d]
__device__ __half g_kv_lo[(size_t)4 * N_HEADS * S_LEN * HD];
__device__ __half g_o_h[(size_t)ROWS * D_MODEL];               // O single fp16

// ---------------------------------------------------------------- helpers
__device__ __forceinline__ uint32_t smem_u32(const void* p) {
    uint32_t a;
    asm("{ .reg .u64 t; cvta.to.shared.u64 t, %1; cvt.u32.u64 %0, t; }" : "=r"(a) : "l"(p));
    return a;
}
__device__ __forceinline__ void cp16(uint32_t saddr, const void* gptr) {
    asm volatile("cp.async.cg.shared.global [%0], [%1], 16;"
                 :: "r"(saddr), "l"(__cvta_generic_to_global(gptr)) : "memory");
}
#define CP_COMMIT() asm volatile("cp.async.commit_group;" ::: "memory")
#define CP_WAIT0()  asm volatile("cp.async.wait_group 0;" ::: "memory")
#define CP_WAIT1()  asm volatile("cp.async.wait_group 1;" ::: "memory")

#define LDM4(r, addr)                                                        \
    asm volatile("ldmatrix.sync.aligned.m8n8.x4.shared.b16 {%0,%1,%2,%3}, [%4];" \
        : "=r"((r)[0]), "=r"((r)[1]), "=r"((r)[2]), "=r"((r)[3]) : "r"(addr))
#define LDM4T(r, addr)                                                       \
    asm volatile("ldmatrix.sync.aligned.m8n8.x4.trans.shared.b16 {%0,%1,%2,%3}, [%4];" \
        : "=r"((r)[0]), "=r"((r)[1]), "=r"((r)[2]), "=r"((r)[3]) : "r"(addr))
#define MMA_F16(d, a, b0, b1)                                                \
    asm volatile("mma.sync.aligned.m16n8k16.row.col.f32.f16.f16.f32 "        \
        "{%0,%1,%2,%3}, {%4,%5,%6,%7}, {%8,%9}, {%0,%1,%2,%3};"              \
        : "+f"((d)[0]), "+f"((d)[1]), "+f"((d)[2]), "+f"((d)[3])             \
        : "r"((a)[0]), "r"((a)[1]), "r"((a)[2]), "r"((a)[3]),                \
          "r"(b0), "r"(b1))

__device__ __forceinline__ uint32_t pack2h(float a, float b) {
    __half2 h = __floats2half2_rn(a, b);
    return *(uint32_t*)&h;
}
// split pair -> packed fp16 hi, packed fp16 lo (residual)
__device__ __forceinline__ uint32_t split2h(float a, float b, uint32_t& lo) {
    __half ha = __float2half_rn(a), hb = __float2half_rn(b);
    lo = pack2h(a - __half2float(ha), b - __half2float(hb));
    return ((uint32_t)__half_as_ushort(hb) << 16) | __half_as_ushort(ha);
}

// fast 2^t for t <= 0, FMA-pipe only. rel err ~2.4e-6.
__device__ __forceinline__ float exp2_fast(float t) {
    t = fmaxf(t, -126.0f);
    float r = t + 12582912.0f;
    float f = t - (r - 12582912.0f);
    int n_i = __float_as_int(r) - 0x4B400000;
    float p = 1.3333558e-3f;
    p = fmaf(p, f, 9.6181291e-3f);
    p = fmaf(p, f, 5.5504109e-2f);
    p = fmaf(p, f, 2.4022651e-1f);
    p = fmaf(p, f, 6.9314718e-1f);
    p = fmaf(p, f, 1.0f);
    return p * __int_as_float((n_i + 127) << 23);
}

// ---------------------------------------------------------------- weight prep
__global__ __launch_bounds__(1024) void build_weffT_hl(
    const float* __restrict__ w,
    const float* __restrict__ qa1, const float* __restrict__ qa2,
    const float* __restrict__ va1, const float* __restrict__ va2) {
    __shared__ float t[32][33];
    int tx = threadIdx.x, ty = threadIdx.y;
    int n0 = blockIdx.x * 32, d0 = blockIdx.y * 32;
    int d = d0 + ty, n = n0 + tx;
    float val = w[(size_t)d * N3 + n];
    if (n < D_MODEL) {
        float s = 0.f;
        #pragma unroll
        for (int r = 0; r < 16; r++) s += qa1[d * 16 + r] * qa2[r * D_MODEL + n];
        val += LORA_SCALE * s;
    } else if (n >= 2 * D_MODEL) {
        int nn = n - 2 * D_MODEL;
        float s = 0.f;
        #pragma unroll
        for (int r = 0; r < 16; r++) s += va1[d * 16 + r] * va2[r * D_MODEL + nn];
        val += LORA_SCALE * s;
    }
    t[ty][tx] = val;
    __syncthreads();
    float v = t[tx][ty];
    __half hi = __float2half_rn(v);
    size_t idx = (size_t)(n0 + ty) * D_MODEL + d0 + tx;
    g_wT_hi[idx] = hi;
    g_wT_lo[idx] = __float2half_rn(v - __half2float(hi));
}

__global__ __launch_bounds__(1024) void build_projT_hl(const float* __restrict__ w) {
    __shared__ float t[32][33];
    int tx = threadIdx.x, ty = threadIdx.y;
    int n0 = blockIdx.x * 32, d0 = blockIdx.y * 32;
    t[ty][tx] = w[(size_t)(d0 + ty) * D_MODEL + n0 + tx];
    __syncthreads();
    float v = t[tx][ty];
    __half hi = __float2half_rn(v);
    size_t idx = (size_t)(n0 + ty) * D_MODEL + d0 + tx;
    g_pT_hi[idx] = hi;
    g_pT_lo[idx] = __float2half_rn(v - __half2float(hi));
}

__global__ void split_x(const float* __restrict__ x) {
    size_t i = (size_t)blockIdx.x * blockDim.x + threadIdx.x;
    if (i >= (size_t)ROWS * D_MODEL / 4) return;
    float4 v = *(const float4*)(x + i * 4);
    uint2 h;
    h.x = pack2h(v.x, v.y);
    h.y = pack2h(v.z, v.w);
    *(uint2*)(g_x_h + i * 4) = h;
}

// ---------------------------------------------------------------- fp16 GEMM (A single, B hi/lo, 2 MMAs)
// C[M,N] = A[M,K] @ BT[N,K]^T + bias.  Tile 128x128x32, 3-stage cp.async,
// 1 barrier per k-tile.
// MODE 0: fp32 out. MODE 1: qkv epilogue (q->g_q hi/lo scaled; k/v->present + g_kv)
#define GP          80
#define OFF_A       0
#define OFF_BH      10240
#define OFF_BL      20480
#define GSTAGE      30720
#define G_SMEM      (3 * GSTAGE)    // 92160

template<int MODE>
__global__ __launch_bounds__(256, 2) void mma_gemm_h(
    int N, int K,
    const __half* __restrict__ A,
    const __half* __restrict__ Bhi, const __half* __restrict__ Blo,
    const float* __restrict__ bias, float* __restrict__ C,
    float* __restrict__ present) {
    extern __shared__ char smraw[];
    const uint32_t sbase = smem_u32(smraw);

    const int tid  = threadIdx.x;
    const int wid  = tid >> 5;
    const int lane = tid & 31;
    const int wm   = wid & 3;
    const int wn   = wid >> 2;
    const int m0   = blockIdx.y * 128;
    const int n0   = blockIdx.x * 128;
    const int NK   = K / 32;

    auto load_stage = [&](int kt, int bf) {
        const uint32_t s0 = sbase + bf * GSTAGE;
        #pragma unroll
        for (int j = 0; j < 6; j++) {
            int c   = tid + j * 256;
            int arr = c >> 9;                  // 0 A, 1 Bhi, 2 Blo
            int rem = c & 511;
            int r   = rem >> 2, p = rem & 3;
            uint32_t sa = s0 + arr * 10240 + r * GP + p * 16;
            const __half* gb;
            if      (arr == 0) gb = A   + (size_t)(m0 + r) * K;
            else if (arr == 1) gb = Bhi + (size_t)(n0 + r) * K;
            else               gb = Blo + (size_t)(n0 + r) * K;
            cp16(sa, (const char*)gb + kt * 64 + p * 16);
        }
    };

    float acc[2][8][4];
    #pragma unroll
    for (int i = 0; i < 2; i++)
        #pragma unroll
        for (int j = 0; j < 8; j++)
            #pragma unroll
            for (int k = 0; k < 4; k++) acc[i][j][k] = 0.f;

    const int g   = lane >> 3;
    const int lr  = lane & 7;
    const int rowsel = ((g & 1) << 3) + lr;
    const int kg  = (g >> 1) << 4;

    load_stage(0, 0); CP_COMMIT();
    load_stage(1, 1); CP_COMMIT();

    int bf = 0, nxt = 2;
    for (int kt = 0; kt < NK; kt++) {
        CP_WAIT1();            // stage kt ready (kt+1 may still be in flight)
        __syncthreads();       // all warps past compute(kt-1); buffer(nxt) free
        if (kt + 2 < NK) {
            load_stage(kt + 2, nxt);
            CP_COMMIT();
        }
        const uint32_t bufb = sbase + bf * GSTAGE;
        #pragma unroll
        for (int ks = 0; ks < 2; ks++) {
            const uint32_t koff = ks * 32 + kg;
            uint32_t af[2][4];
            #pragma unroll
            for (int am = 0; am < 2; am++)
                LDM4(af[am], bufb + OFF_A + (wm * 32 + am * 16 + rowsel) * GP + koff);
            #pragma unroll
            for (int bp = 0; bp < 4; bp++) {
                uint32_t bd = bufb + OFF_BH + (wn * 64 + bp * 16 + rowsel) * GP + koff;
                uint32_t bh[4], bl[4];
                LDM4(bh, bd);
                LDM4(bl, bd + (OFF_BL - OFF_BH));
                #pragma unroll
                for (int am = 0; am < 2; am++) {
                    #pragma unroll
                    for (int sub = 0; sub < 2; sub++) {
                        float* d = acc[am][bp * 2 + sub];
                        MMA_F16(d, af[am], bh[sub], bh[2 + sub]);
                        MMA_F16(d, af[am], bl[sub], bl[2 + sub]);
                    }
                }
            }
        }
        bf = (bf == 2) ? 0 : bf + 1;
        nxt = (nxt == 2) ? 0 : nxt + 1;
    }

    const int rbase = m0 + wm * 32 + (lane >> 2);
    const int cbase = n0 + wn * 64 + (lane & 3) * 2;

    if (MODE == 0) {
        #pragma unroll
        for (int am = 0; am < 2; am++) {
            #pragma unroll
            for (int bn = 0; bn < 8; bn++) {
                int col = cbase + bn * 8;
                float b0 = bias[col], b1 = bias[col + 1];
                int r0 = rbase + am * 16;
                *(float2*)(C + (size_t)r0 * N + col) =
                    make_float2(acc[am][bn][0] + b0, acc[am][bn][1] + b1);
                *(float2*)(C + (size_t)(r0 + 8) * N + col) =
                    make_float2(acc[am][bn][2] + b0, acc[am][bn][3] + b1);
            }
        }
    } else {
        if (blockIdx.x < 8) {
            // q: scale, split fp16 hi/lo
            #pragma unroll
            for (int am = 0; am < 2; am++) {
                #pragma unroll
                for (int bn = 0; bn < 8; bn++) {
                    int col = cbase + bn * 8;
                    float b0 = bias[col], b1 = bias[col + 1];
                    int r0 = rbase + am * 16;
                    float y00 = (acc[am][bn][0] + b0) * QSCALE;
                    float y01 = (acc[am][bn][1] + b1) * QSCALE;
                    float y10 = (acc[am][bn][2] + b0) * QSCALE;
                    float y11 = (acc[am][bn][3] + b1) * QSCALE;
                    uint32_t lo0, lo1;
                    uint32_t hi0 = split2h(y00, y01, lo0);
                    uint32_t hi1 = split2h(y10, y11, lo1);
                    size_t i0 = (size_t)r0 * D_MODEL + col;
                    size_t i1 = (size_t)(r0 + 8) * D_MODEL + col;
                    *(uint32_t*)(g_q_hi + i0) = hi0;
                    *(uint32_t*)(g_q_lo + i0) = lo0;
                    *(uint32_t*)(g_q_hi + i1) = hi1;
                    *(uint32_t*)(g_q_lo + i1) = lo1;
                }
            }
        } else {
            const int cc = (blockIdx.x >= 16) ? 1 : 0;
            const int bb = m0 >> 11;
            const size_t cb_off = (size_t)((cc * 2 + bb) * 16) * 131072;
            #pragma unroll
            for (int am = 0; am < 2; am++) {
                #pragma unroll
                for (int bn = 0; bn < 8; bn++) {
                    int col = cbase + bn * 8;
                    int nn  = col - D_MODEL - cc * D_MODEL;
                    int h   = nn >> 6, d = nn & 63;
                    float b0 = bias[col], b1 = bias[col + 1];
                    int r0 = rbase + am * 16;
                    int s0 = r0 & 2047;
                    float y00 = acc[am][bn][0] + b0;
                    float y01 = acc[am][bn][1] + b1;
                    float y10 = acc[am][bn][2] + b0;
                    float y11 = acc[am][bn][3] + b1;
                    size_t i0 = cb_off + (size_t)h * 131072 + (size_t)s0 * 64 + d;
                    size_t i1 = i0 + 8 * 64;
                    *(float2*)(present + i0) = make_float2(y00, y01);
                    *(float2*)(present + i1) = make_float2(y10, y11);
                    uint32_t lo0, lo1;
                    uint32_t hi0 = split2h(y00, y01, lo0);
                    uint32_t hi1 = split2h(y10, y11, lo1);
                    *(uint32_t*)(g_kv_hi + i0) = hi0;
                    *(uint32_t*)(g_kv_lo + i0) = lo0;
                    *(uint32_t*)(g_kv_hi + i1) = hi1;
                    *(uint32_t*)(g_kv_lo + i1) = lo1;
                }
            }
        }
    }
}

// ---------------------------------------------------------------- flash attention
// BM=128 (8 warps x 16 rows), BN=64. S = 3-term fp16 (Q,K split). PV = 2-term
// (P single fp16, V split). O -> g_o_h single fp16. 2-stage cp.async, 1 barrier/tile.
#define FP       144
#define FKHI     0
#define FKLO     9216
#define FVHI     18432
#define FVLO     27648
#define FSTAGE   36864
#define FQHI     73728                 // 128 rows x 144
#define FQLO     92160
#define F_SMEM   110592

__global__ __launch_bounds__(256, 2) void flash_mma() {
    extern __shared__ char sm[];
    const uint32_t sb = smem_u32(sm);
    const int tid  = threadIdx.x;
    const int wid  = tid >> 5;
    const int lane = tid & 31;
    const int b  = blockIdx.y >> 4;
    const int h  = blockIdx.y & 15;
    const int q0 = blockIdx.x * 128;

    const size_t kbase = (size_t)(b * 16 + h) * 131072;
    const size_t vbase = (size_t)((2 + b) * 16 + h) * 131072;

    // Q tile (fp16 hi/lo), 128 rows
    {
        #pragma unroll
        for (int j = 0; j < 8; j++) {
            int c = tid + j * 256;
            int arr = c >> 10;
            int rem = c & 1023;
            int r = rem >> 3, p = rem & 7;
            uint32_t sa = sb + FQHI + arr * 18432 + r * FP + p * 16;
            const __half* src = (arr ? g_q_lo : g_q_hi)
                + (size_t)(b * S_LEN + q0 + r) * D_MODEL + h * HD;
            cp16(sa, (const char*)src + p * 16);
        }
    }

    auto load_kv = [&](int t, int stg) {
        const uint32_t s0 = sb + stg * FSTAGE;
        const int k0 = t * 64;
        #pragma unroll
        for (int j = 0; j < 8; j++) {
            int c = tid + j * 256;
            int arr = c >> 9;               // 0 Khi 1 Klo 2 Vhi 3 Vlo
            int rem = c & 511;
            int r = rem >> 3, p = rem & 7;
            uint32_t sa = s0 + arr * 9216 + r * FP + p * 16;
            const __half* gb;
            if      (arr == 0) gb = g_kv_hi + kbase;
            else if (arr == 1) gb = g_kv_lo + kbase;
            else if (arr == 2) gb = g_kv_hi + vbase;
            else               gb = g_kv_lo + vbase;
            cp16(sa, (const char*)gb + (size_t)(k0 + r) * 128 + p * 16);
        }
    };

    load_kv(0, 0);
    CP_COMMIT();

    const int g   = lane >> 3;
    const int lr  = lane & 7;
    const int rowsel = ((g & 1) << 3) + lr;
    const int kg  = (g >> 1) << 4;
    const uint32_t vlanebase = (lane & 15) * FP + ((lane >> 4) << 4);
    const int row0 = q0 + wid * 16 + (lane >> 2);

    float o[4][2][4];
    #pragma unroll
    for (int i = 0; i < 4; i++)
        #pragma unroll
        for (int j = 0; j < 2; j++)
            #pragma unroll
            for (int k = 0; k < 4; k++) o[i][j][k] = 0.f;
    float m0r = -1e30f, m1r = -1e30f, l0 = 0.f, l1 = 0.f;

    const int nT = 2 * blockIdx.x + 2;
    for (int t = 0; t < nT; t++) {
        CP_WAIT0();
        __syncthreads();
        if (t + 1 < nT) {
            load_kv(t + 1, (t + 1) & 1);
            CP_COMMIT();
        }
        const uint32_t st = sb + (t & 1) * FSTAGE;
        const int k0 = t * 64;

        // ---- S = Q K^T (3-term fp16)
        float s[4][2][4];
        #pragma unroll
        for (int i = 0; i < 4; i++)
            #pragma unroll
            for (int j = 0; j < 2; j++)
                #pragma unroll
                for (int k = 0; k < 4; k++) s[i][j][k] = 0.f;

        #pragma unroll
        for (int ds = 0; ds < 4; ds++) {
            uint32_t qh[4], ql[4];
            uint32_t qa = sb + FQHI + (wid * 16 + rowsel) * FP + ds * 32 + kg;
            LDM4(qh, qa);
            LDM4(ql, qa + (FQLO - FQHI));
            #pragma unroll
            for (int nt = 0; nt < 4; nt++) {
                uint32_t bd = st + FKHI + (nt * 16 + rowsel) * FP + ds * 32 + kg;
                uint32_t bh[4], bl[4];
                LDM4(bh, bd);
                LDM4(bl, bd + (FKLO - FKHI));
                #pragma unroll
                for (int sub = 0; sub < 2; sub++) {
                    float* d = s[nt][sub];
                    MMA_F16(d, qh, bh[sub], bh[2 + sub]);
                    MMA_F16(d, qh, bl[sub], bl[2 + sub]);
                    MMA_F16(d, ql, bh[sub], bh[2 + sub]);
                }
            }
        }

        // ---- causal mask (last two tiles touch/cross the diagonal band)
        if (t >= nT - 2) {
            #pragma unroll
            for (int nt = 0; nt < 4; nt++)
                #pragma unroll
                for (int sub = 0; sub < 2; sub++) {
                    int colb = k0 + nt * 16 + sub * 8 + (lane & 3) * 2;
                    if (colb     > row0)     s[nt][sub][0] = -1e30f;
                    if (colb + 1 > row0)     s[nt][sub][1] = -1e30f;
                    if (colb     > row0 + 8) s[nt][sub][2] = -1e30f;
                    if (colb + 1 > row0 + 8) s[nt][sub][3] = -1e30f;
                }
        }

        // ---- online softmax (exp2 domain)
        float mx0 = -1e30f, mx1 = -1e30f;
        #pragma unroll
        for (int nt = 0; nt < 4; nt++)
            #pragma unroll
            for (int sub = 0; sub < 2; sub++) {
                mx0 = fmaxf(mx0, fmaxf(s[nt][sub][0], s[nt][sub][1]));
                mx1 = fmaxf(mx1, fmaxf(s[nt][sub][2], s[nt][sub][3]));
            }
        mx0 = fmaxf(mx0, __shfl_xor_sync(0xffffffffu, mx0, 1));
        mx0 = fmaxf(mx0, __shfl_xor_sync(0xffffffffu, mx0, 2));
        mx1 = fmaxf(mx1, __shfl_xor_sync(0xffffffffu, mx1, 1));
        mx1 = fmaxf(mx1, __shfl_xor_sync(0xffffffffu, mx1, 2));
        float nm0 = fmaxf(m0r, mx0), nm1 = fmaxf(m1r, mx1);
        float c0 = exp2_fast(m0r - nm0), c1 = exp2_fast(m1r - nm1);
        m0r = nm0; m1r = nm1;

        float rs0 = 0.f, rs1 = 0.f;
        uint32_t pa[4][4];
        #pragma unroll
        for (int kc = 0; kc < 4; kc++) {
            #pragma unroll
            for (int sub = 0; sub < 2; sub++) {
                float p0 = exp2_fast(s[kc][sub][0] - nm0);
                float p1 = exp2_fast(s[kc][sub][1] - nm0);
                float p2 = exp2_fast(s[kc][sub][2] - nm1);
                float p3 = exp2_fast(s[kc][sub][3] - nm1);
                rs0 += p0 + p1;
                rs1 += p2 + p3;
                pa[kc][sub * 2 + 0] = pack2h(p0, p1);
                pa[kc][sub * 2 + 1] = pack2h(p2, p3);
            }
        }
        rs0 += __shfl_xor_sync(0xffffffffu, rs0, 1);
        rs0 += __shfl_xor_sync(0xffffffffu, rs0, 2);
        rs1 += __shfl_xor_sync(0xffffffffu, rs1, 1);
        rs1 += __shfl_xor_sync(0xffffffffu, rs1, 2);
        l0 = l0 * c0 + rs0;
        l1 = l1 * c1 + rs1;

        #pragma unroll
        for (int dt = 0; dt < 4; dt++)
            #pragma unroll
            for (int sub = 0; sub < 2; sub++) {
                o[dt][sub][0] *= c0; o[dt][sub][1] *= c0;
                o[dt][sub][2] *= c1; o[dt][sub][3] *= c1;
            }

        // ---- O += P V  (P single, V hi/lo)
        #pragma unroll
        for (int kc = 0; kc < 4; kc++) {
            #pragma unroll
            for (int dt = 0; dt < 4; dt++) {
                uint32_t va = st + FVHI + kc * 16 * FP + dt * 32 + vlanebase;
                uint32_t vh[4], vl[4];
                LDM4T(vh, va);
                LDM4T(vl, va + (FVLO - FVHI));
                #pragma unroll
                for (int sub = 0; sub < 2; sub++) {
                    float* d = o[dt][sub];
                    MMA_F16(d, pa[kc], vh[2 * sub], vh[2 * sub + 1]);
                    MMA_F16(d, pa[kc], vl[2 * sub], vl[2 * sub + 1]);
                }
            }
        }
    }

    // ---- write O as single fp16 (GEMM2 A-operand)
    const float inv0 = 1.0f / l0, inv1 = 1.0f / l1;
    const size_t obase = (size_t)(b * S_LEN) * D_MODEL + h * HD + (lane & 3) * 2;
    #pragma unroll
    for (int dt = 0; dt < 4; dt++)
        #pragma unroll
        for (int sub = 0; sub < 2; sub++) {
            int d = dt * 16 + sub * 8;
            uint32_t h0 = pack2h(o[dt][sub][0] * inv0, o[dt][sub][1] * inv0);
            uint32_t h1 = pack2h(o[dt][sub][2] * inv1, o[dt][sub][3] * inv1);
            *(uint32_t*)(g_o_h + obase + (size_t)row0 * D_MODEL + d)       = h0;
            *(uint32_t*)(g_o_h + obase + (size_t)(row0 + 8) * D_MODEL + d) = h1;
        }
}

// ---------------------------------------------------------------- launcher
extern "C" void kernel_launch(void* const* d_in, const int* in_sizes, int n_in,
                              void* d_out, int out_size) {
    const float* x        = (const float*)d_in[0];
    const float* c_attn_w = (const float*)d_in[1];
    const float* c_attn_b = (const float*)d_in[2];
    const float* c_proj_w = (const float*)d_in[3];
    const float* c_proj_b = (const float*)d_in[4];
    const float* q_a1     = (const float*)d_in[5];
    const float* q_a2     = (const float*)d_in[6];
    const float* v_a1     = (const float*)d_in[7];
    const float* v_a2     = (const float*)d_in[8];

    float* out     = (float*)d_out;
    float* a_out   = out;
    float* present = out + (size_t)ROWS * D_MODEL;

    __half *xh, *whi, *wlo, *phi, *plo, *oh;
    cudaGetSymbolAddress((void**)&xh,  g_x_h);
    cudaGetSymbolAddress((void**)&whi, g_wT_hi);
    cudaGetSymbolAddress((void**)&wlo, g_wT_lo);
    cudaGetSymbolAddress((void**)&phi, g_pT_hi);
    cudaGetSymbolAddress((void**)&plo, g_pT_lo);
    cudaGetSymbolAddress((void**)&oh,  g_o_h);

    cudaFuncSetAttribute(mma_gemm_h<0>, cudaFuncAttributeMaxDynamicSharedMemorySize, G_SMEM);
    cudaFuncSetAttribute(mma_gemm_h<1>, cudaFuncAttributeMaxDynamicSharedMemorySize, G_SMEM);
    cudaFuncSetAttribute(flash_mma, cudaFuncAttributeMaxDynamicSharedMemorySize, F_SMEM);

    // 1) operand prep
    build_weffT_hl<<<dim3(N3 / 32, D_MODEL / 32), dim3(32, 32)>>>(c_attn_w, q_a1, q_a2, v_a1, v_a2);
    build_projT_hl<<<dim3(D_MODEL / 32, D_MODEL / 32), dim3(32, 32)>>>(c_proj_w);
    split_x<<<(ROWS * D_MODEL / 4 + 255) / 256, 256>>>(x);

    // 2) qkv GEMM + fused epilogue
    mma_gemm_h<1><<<dim3(N3 / 128, ROWS / 128), 256, G_SMEM>>>(
        N3, D_MODEL, xh, whi, wlo, c_attn_b, nullptr, present);

    // 3) attention
    flash_mma<<<dim3(S_LEN / 128, B_SZ * N_HEADS), 256, F_SMEM>>>();

    // 4) output projection
    mma_gemm_h<0><<<dim3(D_MODEL / 128, ROWS / 128), 256, G_SMEM>>>(
        D_MODEL, D_MODEL, oh, phi, plo, c_proj_b, a_out, nullptr);
}

// round 7
// speedup vs baseline: 3.6115x; 1.0818x over previous
#include <cuda_runtime.h>
#include <cuda_fp16.h>
#include <cstdint>

// ---------------------------------------------------------------- constants
#define B_SZ    2
#define S_LEN   2048
#define D_MODEL 1024
#define N_HEADS 16
#define HD      64
#define N3      (3 * D_MODEL)
#define ROWS    (B_SZ * S_LEN)
#define LORA_SCALE 0.5f
#define QSCALE  0.18033688011112042f   // 0.125 * log2(e)

// ---------------------------------------------------------------- scratch
__device__ __half g_wT_hi[(size_t)N3 * D_MODEL];
__device__ __half g_wT_lo[(size_t)N3 * D_MODEL];
__device__ __half g_pT_hi[(size_t)D_MODEL * D_MODEL];
__device__ __half g_pT_lo[(size_t)D_MODEL * D_MODEL];
__device__ __half g_x_h[(size_t)ROWS * D_MODEL];               // single fp16
__device__ __half g_q_h[(size_t)ROWS * D_MODEL];               // Q single fp16 (scaled)
__device__ __half g_kv_hi[(size_t)4 * N_HEADS * S_LEN * HD];   // [c,b,h,s,d]
__device__ __half g_kv_lo[(size_t)4 * N_HEADS * S_LEN * HD];
__device__ __half g_o_h[(size_t)ROWS * D_MODEL];               // O single fp16

// ---------------------------------------------------------------- helpers
__device__ __forceinline__ uint32_t smem_u32(const void* p) {
    uint32_t a;
    asm("{ .reg .u64 t; cvta.to.shared.u64 t, %1; cvt.u32.u64 %0, t; }" : "=r"(a) : "l"(p));
    return a;
}
__device__ __forceinline__ void cp16(uint32_t saddr, const void* gptr) {
    asm volatile("cp.async.cg.shared.global [%0], [%1], 16;"
                 :: "r"(saddr), "l"(__cvta_generic_to_global(gptr)) : "memory");
}
#define CP_COMMIT() asm volatile("cp.async.commit_group;" ::: "memory")
#define CP_WAIT0()  asm volatile("cp.async.wait_group 0;" ::: "memory")
#define CP_WAIT1()  asm volatile("cp.async.wait_group 1;" ::: "memory")

#define LDM4(r, addr)                                                        \
    asm volatile("ldmatrix.sync.aligned.m8n8.x4.shared.b16 {%0,%1,%2,%3}, [%4];" \
        : "=r"((r)[0]), "=r"((r)[1]), "=r"((r)[2]), "=r"((r)[3]) : "r"(addr))
#define LDM4T(r, addr)                                                       \
    asm volatile("ldmatrix.sync.aligned.m8n8.x4.trans.shared.b16 {%0,%1,%2,%3}, [%4];" \
        : "=r"((r)[0]), "=r"((r)[1]), "=r"((r)[2]), "=r"((r)[3]) : "r"(addr))
#define MMA_F16(d, a, b0, b1)                                                \
    asm volatile("mma.sync.aligned.m16n8k16.row.col.f32.f16.f16.f32 "        \
        "{%0,%1,%2,%3}, {%4,%5,%6,%7}, {%8,%9}, {%0,%1,%2,%3};"              \
        : "+f"((d)[0]), "+f"((d)[1]), "+f"((d)[2]), "+f"((d)[3])             \
        : "r"((a)[0]), "r"((a)[1]), "r"((a)[2]), "r"((a)[3]),                \
          "r"(b0), "r"(b1))

__device__ __forceinline__ uint32_t pack2h(float a, float b) {
    __half2 h = __floats2half2_rn(a, b);
    return *(uint32_t*)&h;
}
__device__ __forceinline__ uint32_t split2h(float a, float b, uint32_t& lo) {
    __half ha = __float2half_rn(a), hb = __float2half_rn(b);
    lo = pack2h(a - __half2float(ha), b - __half2float(hb));
    return ((uint32_t)__half_as_ushort(hb) << 16) | __half_as_ushort(ha);
}

// fast 2^t for t <= 0, FMA-pipe only. rel err ~2.4e-6.
__device__ __forceinline__ float exp2_fast(float t) {
    t = fmaxf(t, -126.0f);
    float r = t + 12582912.0f;
    float f = t - (r - 12582912.0f);
    int n_i = __float_as_int(r) - 0x4B400000;
    float p = 1.3333558e-3f;
    p = fmaf(p, f, 9.6181291e-3f);
    p = fmaf(p, f, 5.5504109e-2f);
    p = fmaf(p, f, 2.4022651e-1f);
    p = fmaf(p, f, 6.9314718e-1f);
    p = fmaf(p, f, 1.0f);
    return p * __int_as_float((n_i + 127) << 23);
}

// ---------------------------------------------------------------- weight prep
__global__ __launch_bounds__(1024) void build_weffT_hl(
    const float* __restrict__ w,
    const float* __restrict__ qa1, const float* __restrict__ qa2,
    const float* __restrict__ va1, const float* __restrict__ va2) {
    __shared__ float t[32][33];
    int tx = threadIdx.x, ty = threadIdx.y;
    int n0 = blockIdx.x * 32, d0 = blockIdx.y * 32;
    int d = d0 + ty, n = n0 + tx;
    float val = w[(size_t)d * N3 + n];
    if (n < D_MODEL) {
        float s = 0.f;
        #pragma unroll
        for (int r = 0; r < 16; r++) s += qa1[d * 16 + r] * qa2[r * D_MODEL + n];
        val += LORA_SCALE * s;
    } else if (n >= 2 * D_MODEL) {
        int nn = n - 2 * D_MODEL;
        float s = 0.f;
        #pragma unroll
        for (int r = 0; r < 16; r++) s += va1[d * 16 + r] * va2[r * D_MODEL + nn];
        val += LORA_SCALE * s;
    }
    t[ty][tx] = val;
    __syncthreads();
    float v = t[tx][ty];
    __half hi = __float2half_rn(v);
    size_t idx = (size_t)(n0 + ty) * D_MODEL + d0 + tx;
    g_wT_hi[idx] = hi;
    g_wT_lo[idx] = __float2half_rn(v - __half2float(hi));
}

__global__ __launch_bounds__(1024) void build_projT_hl(const float* __restrict__ w) {
    __shared__ float t[32][33];
    int tx = threadIdx.x, ty = threadIdx.y;
    int n0 = blockIdx.x * 32, d0 = blockIdx.y * 32;
    t[ty][tx] = w[(size_t)(d0 + ty) * D_MODEL + n0 + tx];
    __syncthreads();
    float v = t[tx][ty];
    __half hi = __float2half_rn(v);
    size_t idx = (size_t)(n0 + ty) * D_MODEL + d0 + tx;
    g_pT_hi[idx] = hi;
    g_pT_lo[idx] = __float2half_rn(v - __half2float(hi));
}

__global__ void split_x(const float* __restrict__ x) {
    size_t i = (size_t)blockIdx.x * blockDim.x + threadIdx.x;
    if (i >= (size_t)ROWS * D_MODEL / 4) return;
    float4 v = *(const float4*)(x + i * 4);
    uint2 h;
    h.x = pack2h(v.x, v.y);
    h.y = pack2h(v.z, v.w);
    *(uint2*)(g_x_h + i * 4) = h;
}

// ---------------------------------------------------------------- fp16 GEMM
// C = A@B^T + bias. A single fp16, B hi/lo (2 MMAs/atom). 128x128x32 tile,
// 3-stage cp.async, hoisted loader addresses, B-fragment prefetch.
#define GP          80
#define OFF_A       0
#define OFF_BH      10240
#define OFF_BL      20480
#define GSTAGE      30720
#define G_SMEM      (3 * GSTAGE)

template<int MODE>
__global__ __launch_bounds__(256, 2) void mma_gemm_h(
    int N, int K,
    const __half* __restrict__ A,
    const __half* __restrict__ Bhi, const __half* __restrict__ Blo,
    const float* __restrict__ bias, float* __restrict__ C,
    float* __restrict__ present) {
    extern __shared__ char smraw[];
    const uint32_t sbase = smem_u32(smraw);

    const int tid  = threadIdx.x;
    const int wid  = tid >> 5;
    const int lane = tid & 31;
    const int wm   = wid & 3;
    const int wn   = wid >> 2;
    const int m0   = blockIdx.y * 128;
    const int n0   = blockIdx.x * 128;
    const int NK   = K / 32;

    // hoisted loader addressing: 6 cp16 per thread per stage
    uint32_t soff[6];
    const char* gptr[6];
    #pragma unroll
    for (int j = 0; j < 6; j++) {
        int c   = tid + j * 256;
        int arr = c >> 9;
        int rem = c & 511;
        int r   = rem >> 2, p = rem & 3;
        soff[j] = arr * 10240 + r * GP + p * 16;
        const __half* gb;
        if      (arr == 0) gb = A   + (size_t)(m0 + r) * K;
        else if (arr == 1) gb = Bhi + (size_t)(n0 + r) * K;
        else               gb = Blo + (size_t)(n0 + r) * K;
        gptr[j] = (const char*)gb + p * 16;
    }
    auto load_stage = [&](int bf) {
        const uint32_t s0 = sbase + bf * GSTAGE;
        #pragma unroll
        for (int j = 0; j < 6; j++) {
            cp16(s0 + soff[j], gptr[j]);
            gptr[j] += 64;
        }
    };

    float acc[2][8][4];
    #pragma unroll
    for (int i = 0; i < 2; i++)
        #pragma unroll
        for (int j = 0; j < 8; j++)
            #pragma unroll
            for (int k = 0; k < 4; k++) acc[i][j][k] = 0.f;

    const int g   = lane >> 3;
    const int lr  = lane & 7;
    const int rowsel = ((g & 1) << 3) + lr;
    const int kg  = (g >> 1) << 4;

    load_stage(0); CP_COMMIT();
    load_stage(1); CP_COMMIT();

    int bf = 0, nxt = 2;
    for (int kt = 0; kt < NK; kt++) {
        CP_WAIT1();
        __syncthreads();
        if (kt + 2 < NK) {
            load_stage(nxt);
            CP_COMMIT();
        }
        const uint32_t bufb = sbase + bf * GSTAGE;
        #pragma unroll
        for (int ks = 0; ks < 2; ks++) {
            const uint32_t koff = ks * 32 + kg;
            uint32_t af[2][4];
            #pragma unroll
            for (int am = 0; am < 2; am++)
                LDM4(af[am], bufb + OFF_A + (wm * 32 + am * 16 + rowsel) * GP + koff);
            // B fragment double-buffer: prefetch bp+1 during bp's MMAs
            uint32_t bh[2][4], bl[2][4];
            {
                uint32_t bd = bufb + OFF_BH + (wn * 64 + rowsel) * GP + koff;
                LDM4(bh[0], bd);
                LDM4(bl[0], bd + (OFF_BL - OFF_BH));
            }
            #pragma unroll
            for (int bp = 0; bp < 4; bp++) {
                const int cur = bp & 1, alt = cur ^ 1;
                if (bp < 3) {
                    uint32_t bd = bufb + OFF_BH + (wn * 64 + (bp + 1) * 16 + rowsel) * GP + koff;
                    LDM4(bh[alt], bd);
                    LDM4(bl[alt], bd + (OFF_BL - OFF_BH));
                }
                #pragma unroll
                for (int am = 0; am < 2; am++) {
                    #pragma unroll
                    for (int sub = 0; sub < 2; sub++) {
                        float* d = acc[am][bp * 2 + sub];
                        MMA_F16(d, af[am], bh[cur][sub], bh[cur][2 + sub]);
                        MMA_F16(d, af[am], bl[cur][sub], bl[cur][2 + sub]);
                    }
                }
            }
        }
        bf = (bf == 2) ? 0 : bf + 1;
        nxt = (nxt == 2) ? 0 : nxt + 1;
    }

    const int rbase = m0 + wm * 32 + (lane >> 2);
    const int cbase = n0 + wn * 64 + (lane & 3) * 2;

    if (MODE == 0) {
        #pragma unroll
        for (int am = 0; am < 2; am++) {
            #pragma unroll
            for (int bn = 0; bn < 8; bn++) {
                int col = cbase + bn * 8;
                float b0 = bias[col], b1 = bias[col + 1];
                int r0 = rbase + am * 16;
                *(float2*)(C + (size_t)r0 * N + col) =
                    make_float2(acc[am][bn][0] + b0, acc[am][bn][1] + b1);
                *(float2*)(C + (size_t)(r0 + 8) * N + col) =
                    make_float2(acc[am][bn][2] + b0, acc[am][bn][3] + b1);
            }
        }
    } else {
        if (blockIdx.x < 8) {
            // q: scale, single fp16
            #pragma unroll
            for (int am = 0; am < 2; am++) {
                #pragma unroll
                for (int bn = 0; bn < 8; bn++) {
                    int col = cbase + bn * 8;
                    float b0 = bias[col], b1 = bias[col + 1];
                    int r0 = rbase + am * 16;
                    uint32_t h0 = pack2h((acc[am][bn][0] + b0) * QSCALE,
                                         (acc[am][bn][1] + b1) * QSCALE);
                    uint32_t h1 = pack2h((acc[am][bn][2] + b0) * QSCALE,
                                         (acc[am][bn][3] + b1) * QSCALE);
                    *(uint32_t*)(g_q_h + (size_t)r0 * D_MODEL + col)       = h0;
                    *(uint32_t*)(g_q_h + (size_t)(r0 + 8) * D_MODEL + col) = h1;
                }
            }
        } else {
            const int cc = (blockIdx.x >= 16) ? 1 : 0;
            const int bb = m0 >> 11;
            const size_t cb_off = (size_t)((cc * 2 + bb) * 16) * 131072;
            #pragma unroll
            for (int am = 0; am < 2; am++) {
                #pragma unroll
                for (int bn = 0; bn < 8; bn++) {
                    int col = cbase + bn * 8;
                    int nn  = col - D_MODEL - cc * D_MODEL;
                    int h   = nn >> 6, d = nn & 63;
                    float b0 = bias[col], b1 = bias[col + 1];
                    int r0 = rbase + am * 16;
                    int s0 = r0 & 2047;
                    float y00 = acc[am][bn][0] + b0;
                    float y01 = acc[am][bn][1] + b1;
                    float y10 = acc[am][bn][2] + b0;
                    float y11 = acc[am][bn][3] + b1;
                    size_t i0 = cb_off + (size_t)h * 131072 + (size_t)s0 * 64 + d;
                    size_t i1 = i0 + 8 * 64;
                    *(float2*)(present + i0) = make_float2(y00, y01);
                    *(float2*)(present + i1) = make_float2(y10, y11);
                    uint32_t lo0, lo1;
                    uint32_t hi0 = split2h(y00, y01, lo0);
                    uint32_t hi1 = split2h(y10, y11, lo1);
                    *(uint32_t*)(g_kv_hi + i0) = hi0;
                    *(uint32_t*)(g_kv_lo + i0) = lo0;
                    *(uint32_t*)(g_kv_hi + i1) = hi1;
                    *(uint32_t*)(g_kv_lo + i1) = lo1;
                }
            }
        }
    }
}

// ---------------------------------------------------------------- flash attention
// BM=128, BN=64. S = 2-term (Q single, K hi/lo). PV = 2-term (P single, V hi/lo).
// Heavy-first CTA order. 2-stage cp.async, 1 barrier/tile.
#define FP       144
#define FKHI     0
#define FKLO     9216
#define FVHI     18432
#define FVLO     27648
#define FSTAGE   36864
#define FQ       73728                 // 128 rows x 144 (single fp16)
#define F_SMEM   92160

__global__ __launch_bounds__(256, 2) void flash_mma() {
    extern __shared__ char sm[];
    const uint32_t sb = smem_u32(sm);
    const int tid  = threadIdx.x;
    const int wid  = tid >> 5;
    const int lane = tid & 31;
    const int b  = blockIdx.y >> 4;
    const int h  = blockIdx.y & 15;
    const int qi = gridDim.x - 1 - blockIdx.x;   // heavy-first
    const int q0 = qi * 128;

    const size_t kbase = (size_t)(b * 16 + h) * 131072;
    const size_t vbase = (size_t)((2 + b) * 16 + h) * 131072;

    // Q tile (single fp16), 128 rows
    {
        #pragma unroll
        for (int j = 0; j < 4; j++) {
            int c = tid + j * 256;
            int r = c >> 3, p = c & 7;
            uint32_t sa = sb + FQ + r * FP + p * 16;
            const __half* src = g_q_h + (size_t)(b * S_LEN + q0 + r) * D_MODEL + h * HD;
            cp16(sa, (const char*)src + p * 16);
        }
    }

    auto load_kv = [&](int t, int stg) {
        const uint32_t s0 = sb + stg * FSTAGE;
        const int k0 = t * 64;
        #pragma unroll
        for (int j = 0; j < 8; j++) {
            int c = tid + j * 256;
            int arr = c >> 9;               // 0 Khi 1 Klo 2 Vhi 3 Vlo
            int rem = c & 511;
            int r = rem >> 3, p = rem & 7;
            uint32_t sa = s0 + arr * 9216 + r * FP + p * 16;
            const __half* gb;
            if      (arr == 0) gb = g_kv_hi + kbase;
            else if (arr == 1) gb = g_kv_lo + kbase;
            else if (arr == 2) gb = g_kv_hi + vbase;
            else               gb = g_kv_lo + vbase;
            cp16(sa, (const char*)gb + (size_t)(k0 + r) * 128 + p * 16);
        }
    };

    load_kv(0, 0);
    CP_COMMIT();

    const int g   = lane >> 3;
    const int lr  = lane & 7;
    const int rowsel = ((g & 1) << 3) + lr;
    const int kg  = (g >> 1) << 4;
    const uint32_t vlanebase = (lane & 15) * FP + ((lane >> 4) << 4);
    const int row0 = q0 + wid * 16 + (lane >> 2);

    float o[4][2][4];
    #pragma unroll
    for (int i = 0; i < 4; i++)
        #pragma unroll
        for (int j = 0; j < 2; j++)
            #pragma unroll
            for (int k = 0; k < 4; k++) o[i][j][k] = 0.f;
    float m0r = -1e30f, m1r = -1e30f, l0 = 0.f, l1 = 0.f;

    const int nT = 2 * qi + 2;
    for (int t = 0; t < nT; t++) {
        CP_WAIT0();
        __syncthreads();
        if (t + 1 < nT) {
            load_kv(t + 1, (t + 1) & 1);
            CP_COMMIT();
        }
        const uint32_t st = sb + (t & 1) * FSTAGE;
        const int k0 = t * 64;

        // ---- S = Q K^T (Q single, K hi/lo)
        float s[4][2][4];
        #pragma unroll
        for (int i = 0; i < 4; i++)
            #pragma unroll
            for (int j = 0; j < 2; j++)
                #pragma unroll
                for (int k = 0; k < 4; k++) s[i][j][k] = 0.f;

        #pragma unroll
        for (int ds = 0; ds < 4; ds++) {
            uint32_t qh[4];
            LDM4(qh, sb + FQ + (wid * 16 + rowsel) * FP + ds * 32 + kg);
            #pragma unroll
            for (int nt = 0; nt < 4; nt++) {
                uint32_t bd = st + FKHI + (nt * 16 + rowsel) * FP + ds * 32 + kg;
                uint32_t bh[4], bl[4];
                LDM4(bh, bd);
                LDM4(bl, bd + (FKLO - FKHI));
                #pragma unroll
                for (int sub = 0; sub < 2; sub++) {
                    float* d = s[nt][sub];
                    MMA_F16(d, qh, bh[sub], bh[2 + sub]);
                    MMA_F16(d, qh, bl[sub], bl[2 + sub]);
                }
            }
        }

        // ---- causal mask (last two tiles)
        if (t >= nT - 2) {
            #pragma unroll
            for (int nt = 0; nt < 4; nt++)
                #pragma unroll
                for (int sub = 0; sub < 2; sub++) {
                    int colb = k0 + nt * 16 + sub * 8 + (lane & 3) * 2;
                    if (colb     > row0)     s[nt][sub][0] = -1e30f;
                    if (colb + 1 > row0)     s[nt][sub][1] = -1e30f;
                    if (colb     > row0 + 8) s[nt][sub][2] = -1e30f;
                    if (colb + 1 > row0 + 8) s[nt][sub][3] = -1e30f;
                }
        }

        // ---- online softmax (exp2 domain)
        float mx0 = -1e30f, mx1 = -1e30f;
        #pragma unroll
        for (int nt = 0; nt < 4; nt++)
            #pragma unroll
            for (int sub = 0; sub < 2; sub++) {
                mx0 = fmaxf(mx0, fmaxf(s[nt][sub][0], s[nt][sub][1]));
                mx1 = fmaxf(mx1, fmaxf(s[nt][sub][2], s[nt][sub][3]));
            }
        mx0 = fmaxf(mx0, __shfl_xor_sync(0xffffffffu, mx0, 1));
        mx0 = fmaxf(mx0, __shfl_xor_sync(0xffffffffu, mx0, 2));
        mx1 = fmaxf(mx1, __shfl_xor_sync(0xffffffffu, mx1, 1));
        mx1 = fmaxf(mx1, __shfl_xor_sync(0xffffffffu, mx1, 2));
        float nm0 = fmaxf(m0r, mx0), nm1 = fmaxf(m1r, mx1);
        float c0 = exp2_fast(m0r - nm0), c1 = exp2_fast(m1r - nm1);
        m0r = nm0; m1r = nm1;

        float rs0 = 0.f, rs1 = 0.f;
        uint32_t pa[4][4];
        #pragma unroll
        for (int kc = 0; kc < 4; kc++) {
            #pragma unroll
            for (int sub = 0; sub < 2; sub++) {
                float p0 = exp2_fast(s[kc][sub][0] - nm0);
                float p1 = exp2_fast(s[kc][sub][1] - nm0);
                float p2 = exp2_fast(s[kc][sub][2] - nm1);
                float p3 = exp2_fast(s[kc][sub][3] - nm1);
                rs0 += p0 + p1;
                rs1 += p2 + p3;
                pa[kc][sub * 2 + 0] = pack2h(p0, p1);
                pa[kc][sub * 2 + 1] = pack2h(p2, p3);
            }
        }
        rs0 += __shfl_xor_sync(0xffffffffu, rs0, 1);
        rs0 += __shfl_xor_sync(0xffffffffu, rs0, 2);
        rs1 += __shfl_xor_sync(0xffffffffu, rs1, 1);
        rs1 += __shfl_xor_sync(0xffffffffu, rs1, 2);
        l0 = l0 * c0 + rs0;
        l1 = l1 * c1 + rs1;

        #pragma unroll
        for (int dt = 0; dt < 4; dt++)
            #pragma unroll
            for (int sub = 0; sub < 2; sub++) {
                o[dt][sub][0] *= c0; o[dt][sub][1] *= c0;
                o[dt][sub][2] *= c1; o[dt][sub][3] *= c1;
            }

        // ---- O += P V  (P single, V hi/lo)
        #pragma unroll
        for (int kc = 0; kc < 4; kc++) {
            #pragma unroll
            for (int dt = 0; dt < 4; dt++) {
                uint32_t va = st + FVHI + kc * 16 * FP + dt * 32 + vlanebase;
                uint32_t vh[4], vl[4];
                LDM4T(vh, va);
                LDM4T(vl, va + (FVLO - FVHI));
                #pragma unroll
                for (int sub = 0; sub < 2; sub++) {
                    float* d = o[dt][sub];
                    MMA_F16(d, pa[kc], vh[2 * sub], vh[2 * sub + 1]);
                    MMA_F16(d, pa[kc], vl[2 * sub], vl[2 * sub + 1]);
                }
            }
        }
    }

    // ---- write O as single fp16 (GEMM2 A-operand)
    const float inv0 = 1.0f / l0, inv1 = 1.0f / l1;
    const size_t obase = (size_t)(b * S_LEN) * D_MODEL + h * HD + (lane & 3) * 2;
    #pragma unroll
    for (int dt = 0; dt < 4; dt++)
        #pragma unroll
        for (int sub = 0; sub < 2; sub++) {
            int d = dt * 16 + sub * 8;
            uint32_t h0 = pack2h(o[dt][sub][0] * inv0, o[dt][sub][1] * inv0);
            uint32_t h1 = pack2h(o[dt][sub][2] * inv1, o[dt][sub][3] * inv1);
            *(uint32_t*)(g_o_h + obase + (size_t)row0 * D_MODEL + d)       = h0;
            *(uint32_t*)(g_o_h + obase + (size_t)(row0 + 8) * D_MODEL + d) = h1;
        }
}

// ---------------------------------------------------------------- launcher
extern "C" void kernel_launch(void* const* d_in, const int* in_sizes, int n_in,
                              void* d_out, int out_size) {
    const float* x        = (const float*)d_in[0];
    const float* c_attn_w = (const float*)d_in[1];
    const float* c_attn_b = (const float*)d_in[2];
    const float* c_proj_w = (const float*)d_in[3];
    const float* c_proj_b = (const float*)d_in[4];
    const float* q_a1     = (const float*)d_in[5];
    const float* q_a2     = (const float*)d_in[6];
    const float* v_a1     = (const float*)d_in[7];
    const float* v_a2     = (const float*)d_in[8];

    float* out     = (float*)d_out;
    float* a_out   = out;
    float* present = out + (size_t)ROWS * D_MODEL;

    __half *xh, *whi, *wlo, *phi, *plo, *oh;
    cudaGetSymbolAddress((void**)&xh,  g_x_h);
    cudaGetSymbolAddress((void**)&whi, g_wT_hi);
    cudaGetSymbolAddress((void**)&wlo, g_wT_lo);
    cudaGetSymbolAddress((void**)&phi, g_pT_hi);
    cudaGetSymbolAddress((void**)&plo, g_pT_lo);
    cudaGetSymbolAddress((void**)&oh,  g_o_h);

    cudaFuncSetAttribute(mma_gemm_h<0>, cudaFuncAttributeMaxDynamicSharedMemorySize, G_SMEM);
    cudaFuncSetAttribute(mma_gemm_h<1>, cudaFuncAttributeMaxDynamicSharedMemorySize, G_SMEM);
    cudaFuncSetAttribute(flash_mma, cudaFuncAttributeMaxDynamicSharedMemorySize, F_SMEM);

    // 1) operand prep
    build_weffT_hl<<<dim3(N3 / 32, D_MODEL / 32), dim3(32, 32)>>>(c_attn_w, q_a1, q_a2, v_a1, v_a2);
    build_projT_hl<<<dim3(D_MODEL / 32, D_MODEL / 32), dim3(32, 32)>>>(c_proj_w);
    split_x<<<(ROWS * D_MODEL / 4 + 255) / 256, 256>>>(x);

    // 2) qkv GEMM + fused epilogue
    mma_gemm_h<1><<<dim3(N3 / 128, ROWS / 128), 256, G_SMEM>>>(
        N3, D_MODEL, xh, whi, wlo, c_attn_b, nullptr, present);

    // 3) attention
    flash_mma<<<dim3(S_LEN / 128, B_SZ * N_HEADS), 256, F_SMEM>>>();

    // 4) output projection
    mma_gemm_h<0><<<dim3(D_MODEL / 128, ROWS / 128), 256, G_SMEM>>>(
        D_MODEL, D_MODEL, oh, phi, plo, c_proj_b, a_out, nullptr);
}

// round 8
// speedup vs baseline: 5.6266x; 1.5580x over previous
#include <cuda_runtime.h>
#include <cuda_fp16.h>
#include <cstdint>

// ---------------------------------------------------------------- constants
#define B_SZ    2
#define S_LEN   2048
#define D_MODEL 1024
#define N_HEADS 16
#define HD      64
#define N3      (3 * D_MODEL)
#define ROWS    (B_SZ * S_LEN)
#define LORA_SCALE 0.5f
#define QSCALE  0.18033688011112042f   // 0.125 * log2(e)

// ---------------------------------------------------------------- scratch (all single fp16)
__device__ __half g_wT_h[(size_t)N3 * D_MODEL];
__device__ __half g_pT_h[(size_t)D_MODEL * D_MODEL];
__device__ __half g_x_h[(size_t)ROWS * D_MODEL];
__device__ __half g_q_h[(size_t)ROWS * D_MODEL];               // scaled by QSCALE
__device__ __half g_kv_h[(size_t)4 * N_HEADS * S_LEN * HD];    // [c,b,h,s,d]
__device__ __half g_o_h[(size_t)ROWS * D_MODEL];

// ---------------------------------------------------------------- helpers
__device__ __forceinline__ uint32_t smem_u32(const void* p) {
    uint32_t a;
    asm("{ .reg .u64 t; cvta.to.shared.u64 t, %1; cvt.u32.u64 %0, t; }" : "=r"(a) : "l"(p));
    return a;
}
__device__ __forceinline__ void cp16(uint32_t saddr, const void* gptr) {
    asm volatile("cp.async.cg.shared.global [%0], [%1], 16;"
                 :: "r"(saddr), "l"(__cvta_generic_to_global(gptr)) : "memory");
}
#define CP_COMMIT() asm volatile("cp.async.commit_group;" ::: "memory")
#define CP_WAIT1()  asm volatile("cp.async.wait_group 1;" ::: "memory")

#define LDM4(r, addr)                                                        \
    asm volatile("ldmatrix.sync.aligned.m8n8.x4.shared.b16 {%0,%1,%2,%3}, [%4];" \
        : "=r"((r)[0]), "=r"((r)[1]), "=r"((r)[2]), "=r"((r)[3]) : "r"(addr))
#define LDM4T(r, addr)                                                       \
    asm volatile("ldmatrix.sync.aligned.m8n8.x4.trans.shared.b16 {%0,%1,%2,%3}, [%4];" \
        : "=r"((r)[0]), "=r"((r)[1]), "=r"((r)[2]), "=r"((r)[3]) : "r"(addr))
#define MMA_F16(d, a, b0, b1)                                                \
    asm volatile("mma.sync.aligned.m16n8k16.row.col.f32.f16.f16.f32 "        \
        "{%0,%1,%2,%3}, {%4,%5,%6,%7}, {%8,%9}, {%0,%1,%2,%3};"              \
        : "+f"((d)[0]), "+f"((d)[1]), "+f"((d)[2]), "+f"((d)[3])             \
        : "r"((a)[0]), "r"((a)[1]), "r"((a)[2]), "r"((a)[3]),                \
          "r"(b0), "r"(b1))

__device__ __forceinline__ uint32_t pack2h(float a, float b) {
    __half2 h = __floats2half2_rn(a, b);
    return *(uint32_t*)&h;
}

// fast 2^t for t <= 0, FMA-pipe only. rel err ~2.4e-6.
__device__ __forceinline__ float exp2_fast(float t) {
    t = fmaxf(t, -126.0f);
    float r = t + 12582912.0f;
    float f = t - (r - 12582912.0f);
    int n_i = __float_as_int(r) - 0x4B400000;
    float p = 1.3333558e-3f;
    p = fmaf(p, f, 9.6181291e-3f);
    p = fmaf(p, f, 5.5504109e-2f);
    p = fmaf(p, f, 2.4022651e-1f);
    p = fmaf(p, f, 6.9314718e-1f);
    p = fmaf(p, f, 1.0f);
    return p * __int_as_float((n_i + 127) << 23);
}

// ---------------------------------------------------------------- weight prep
__global__ __launch_bounds__(1024) void build_weffT_h(
    const float* __restrict__ w,
    const float* __restrict__ qa1, const float* __restrict__ qa2,
    const float* __restrict__ va1, const float* __restrict__ va2) {
    __shared__ float t[32][33];
    int tx = threadIdx.x, ty = threadIdx.y;
    int n0 = blockIdx.x * 32, d0 = blockIdx.y * 32;
    int d = d0 + ty, n = n0 + tx;
    float val = w[(size_t)d * N3 + n];
    if (n < D_MODEL) {
        float s = 0.f;
        #pragma unroll
        for (int r = 0; r < 16; r++) s += qa1[d * 16 + r] * qa2[r * D_MODEL + n];
        val += LORA_SCALE * s;
    } else if (n >= 2 * D_MODEL) {
        int nn = n - 2 * D_MODEL;
        float s = 0.f;
        #pragma unroll
        for (int r = 0; r < 16; r++) s += va1[d * 16 + r] * va2[r * D_MODEL + nn];
        val += LORA_SCALE * s;
    }
    t[ty][tx] = val;
    __syncthreads();
    g_wT_h[(size_t)(n0 + ty) * D_MODEL + d0 + tx] = __float2half_rn(t[tx][ty]);
}

__global__ __launch_bounds__(1024) void build_projT_h(const float* __restrict__ w) {
    __shared__ float t[32][33];
    int tx = threadIdx.x, ty = threadIdx.y;
    int n0 = blockIdx.x * 32, d0 = blockIdx.y * 32;
    t[ty][tx] = w[(size_t)(d0 + ty) * D_MODEL + n0 + tx];
    __syncthreads();
    g_pT_h[(size_t)(n0 + ty) * D_MODEL + d0 + tx] = __float2half_rn(t[tx][ty]);
}

__global__ void split_x(const float* __restrict__ x) {
    size_t i = (size_t)blockIdx.x * blockDim.x + threadIdx.x;
    if (i >= (size_t)ROWS * D_MODEL / 4) return;
    float4 v = *(const float4*)(x + i * 4);
    uint2 h;
    h.x = pack2h(v.x, v.y);
    h.y = pack2h(v.z, v.w);
    *(uint2*)(g_x_h + i * 4) = h;
}

// ---------------------------------------------------------------- fp16 GEMM (single/single, 1 MMA/atom)
// C = A@B^T + bias. 128x128x32 tile, 3-stage cp.async, always-commit pipeline.
#define GP          80
#define OFF_A       0
#define OFF_B       10240
#define GSTAGE      20480
#define G_SMEM      (3 * GSTAGE)    // 61440

template<int MODE>
__global__ __launch_bounds__(256, 2) void mma_gemm_h(
    int N, int K,
    const __half* __restrict__ A, const __half* __restrict__ B,
    const float* __restrict__ bias, float* __restrict__ C,
    float* __restrict__ present) {
    extern __shared__ char smraw[];
    const uint32_t sbase = smem_u32(smraw);

    const int tid  = threadIdx.x;
    const int wid  = tid >> 5;
    const int lane = tid & 31;
    const int wm   = wid & 3;
    const int wn   = wid >> 2;
    const int m0   = blockIdx.y * 128;
    const int n0   = blockIdx.x * 128;
    const int NK   = K / 32;

    // hoisted loader addressing: 4 cp16 per thread per stage
    uint32_t soff[4];
    const char* gptr[4];
    #pragma unroll
    for (int j = 0; j < 4; j++) {
        int c   = tid + j * 256;
        int arr = c >> 9;                  // 0 A, 1 B
        int rem = c & 511;
        int r   = rem >> 2, p = rem & 3;
        soff[j] = arr * 10240 + r * GP + p * 16;
        const __half* gb = arr ? (B + (size_t)(n0 + r) * K) : (A + (size_t)(m0 + r) * K);
        gptr[j] = (const char*)gb + p * 16;
    }
    auto load_stage = [&](int bf) {
        const uint32_t s0 = sbase + bf * GSTAGE;
        #pragma unroll
        for (int j = 0; j < 4; j++) {
            cp16(s0 + soff[j], gptr[j]);
            gptr[j] += 64;
        }
    };

    float acc[2][8][4];
    #pragma unroll
    for (int i = 0; i < 2; i++)
        #pragma unroll
        for (int j = 0; j < 8; j++)
            #pragma unroll
            for (int k = 0; k < 4; k++) acc[i][j][k] = 0.f;

    const int g   = lane >> 3;
    const int lr  = lane & 7;
    const int rowsel = ((g & 1) << 3) + lr;
    const int kg  = (g >> 1) << 4;

    load_stage(0); CP_COMMIT();
    load_stage(1); CP_COMMIT();

    int bf = 0, nxt = 2;
    for (int kt = 0; kt < NK; kt++) {
        CP_WAIT1();            // stage kt guaranteed (always-commit invariant)
        __syncthreads();
        if (kt + 2 < NK) load_stage(nxt);
        CP_COMMIT();           // always commit: keeps wait_group accounting exact
        const uint32_t bufb = sbase + bf * GSTAGE;
        #pragma unroll
        for (int ks = 0; ks < 2; ks++) {
            const uint32_t koff = ks * 32 + kg;
            uint32_t af[2][4];
            #pragma unroll
            for (int am = 0; am < 2; am++)
                LDM4(af[am], bufb + OFF_A + (wm * 32 + am * 16 + rowsel) * GP + koff);
            uint32_t bfrag[2][4];
            LDM4(bfrag[0], bufb + OFF_B + (wn * 64 + rowsel) * GP + koff);
            #pragma unroll
            for (int bp = 0; bp < 4; bp++) {
                const int cur = bp & 1, alt = cur ^ 1;
                if (bp < 3)
                    LDM4(bfrag[alt], bufb + OFF_B + (wn * 64 + (bp + 1) * 16 + rowsel) * GP + koff);
                #pragma unroll
                for (int am = 0; am < 2; am++)
                    #pragma unroll
                    for (int sub = 0; sub < 2; sub++)
                        MMA_F16(acc[am][bp * 2 + sub], af[am],
                                bfrag[cur][sub], bfrag[cur][2 + sub]);
            }
        }
        bf  = (bf  == 2) ? 0 : bf  + 1;
        nxt = (nxt == 2) ? 0 : nxt + 1;
    }

    const int rbase = m0 + wm * 32 + (lane >> 2);
    const int cbase = n0 + wn * 64 + (lane & 3) * 2;

    if (MODE == 0) {
        #pragma unroll
        for (int am = 0; am < 2; am++) {
            #pragma unroll
            for (int bn = 0; bn < 8; bn++) {
                int col = cbase + bn * 8;
                float b0 = bias[col], b1 = bias[col + 1];
                int r0 = rbase + am * 16;
                *(float2*)(C + (size_t)r0 * N + col) =
                    make_float2(acc[am][bn][0] + b0, acc[am][bn][1] + b1);
                *(float2*)(C + (size_t)(r0 + 8) * N + col) =
                    make_float2(acc[am][bn][2] + b0, acc[am][bn][3] + b1);
            }
        }
    } else {
        if (blockIdx.x < 8) {
            // q: scale, single fp16
            #pragma unroll
            for (int am = 0; am < 2; am++) {
                #pragma unroll
                for (int bn = 0; bn < 8; bn++) {
                    int col = cbase + bn * 8;
                    float b0 = bias[col], b1 = bias[col + 1];
                    int r0 = rbase + am * 16;
                    uint32_t h0 = pack2h((acc[am][bn][0] + b0) * QSCALE,
                                         (acc[am][bn][1] + b1) * QSCALE);
                    uint32_t h1 = pack2h((acc[am][bn][2] + b0) * QSCALE,
                                         (acc[am][bn][3] + b1) * QSCALE);
                    *(uint32_t*)(g_q_h + (size_t)r0 * D_MODEL + col)       = h0;
                    *(uint32_t*)(g_q_h + (size_t)(r0 + 8) * D_MODEL + col) = h1;
                }
            }
        } else {
            const int cc = (blockIdx.x >= 16) ? 1 : 0;
            const int bb = m0 >> 11;
            const size_t cb_off = (size_t)((cc * 2 + bb) * 16) * 131072;
            #pragma unroll
            for (int am = 0; am < 2; am++) {
                #pragma unroll
                for (int bn = 0; bn < 8; bn++) {
                    int col = cbase + bn * 8;
                    int nn  = col - D_MODEL - cc * D_MODEL;
                    int h   = nn >> 6, d = nn & 63;
                    float b0 = bias[col], b1 = bias[col + 1];
                    int r0 = rbase + am * 16;
                    int s0 = r0 & 2047;
                    float y00 = acc[am][bn][0] + b0;
                    float y01 = acc[am][bn][1] + b1;
                    float y10 = acc[am][bn][2] + b0;
                    float y11 = acc[am][bn][3] + b1;
                    size_t i0 = cb_off + (size_t)h * 131072 + (size_t)s0 * 64 + d;
                    size_t i1 = i0 + 8 * 64;
                    *(float2*)(present + i0) = make_float2(y00, y01);
                    *(float2*)(present + i1) = make_float2(y10, y11);
                    *(uint32_t*)(g_kv_h + i0) = pack2h(y00, y01);
                    *(uint32_t*)(g_kv_h + i1) = pack2h(y10, y11);
                }
            }
        }
    }
}

// ---------------------------------------------------------------- flash attention
// BM=128, BN=64. All operands single fp16. 3-stage KV cp.async, heavy-first.
#define FP       144
#define FK       0
#define FV       9216
#define FSTAGE   18432
#define FQ       55296                 // 3 stages then Q (128 x 144)
#define F_SMEM   73728

__global__ __launch_bounds__(256, 2) void flash_mma() {
    extern __shared__ char sm[];
    const uint32_t sb = smem_u32(sm);
    const int tid  = threadIdx.x;
    const int wid  = tid >> 5;
    const int lane = tid & 31;
    const int b  = blockIdx.y >> 4;
    const int h  = blockIdx.y & 15;
    const int qi = gridDim.x - 1 - blockIdx.x;   // heavy-first
    const int q0 = qi * 128;

    const size_t kbase = (size_t)(b * 16 + h) * 131072;
    const size_t vbase = (size_t)((2 + b) * 16 + h) * 131072;

    auto load_kv = [&](int t, int stg) {
        const uint32_t s0 = sb + stg * FSTAGE;
        const int k0 = t * 64;
        #pragma unroll
        for (int j = 0; j < 4; j++) {
            int c = tid + j * 256;
            int arr = c >> 9;               // 0 K, 1 V
            int rem = c & 511;
            int r = rem >> 3, p = rem & 7;
            uint32_t sa = s0 + arr * 9216 + r * FP + p * 16;
            const __half* gb = g_kv_h + (arr ? vbase : kbase);
            cp16(sa, (const char*)gb + (size_t)(k0 + r) * 128 + p * 16);
        }
    };

    // group 0: Q + KV stage 0 ; group 1: KV stage 1
    {
        #pragma unroll
        for (int j = 0; j < 4; j++) {
            int c = tid + j * 256;
            int r = c >> 3, p = c & 7;
            uint32_t sa = sb + FQ + r * FP + p * 16;
            const __half* src = g_q_h + (size_t)(b * S_LEN + q0 + r) * D_MODEL + h * HD;
            cp16(sa, (const char*)src + p * 16);
        }
    }
    load_kv(0, 0); CP_COMMIT();
    const int nT = 2 * qi + 2;
    if (1 < nT) load_kv(1, 1);
    CP_COMMIT();

    const int g   = lane >> 3;
    const int lr  = lane & 7;
    const int rowsel = ((g & 1) << 3) + lr;
    const int kg  = (g >> 1) << 4;
    const uint32_t vlanebase = (lane & 15) * FP + ((lane >> 4) << 4);
    const int row0 = q0 + wid * 16 + (lane >> 2);

    float o[4][2][4];
    #pragma unroll
    for (int i = 0; i < 4; i++)
        #pragma unroll
        for (int j = 0; j < 2; j++)
            #pragma unroll
            for (int k = 0; k < 4; k++) o[i][j][k] = 0.f;
    float m0r = -1e30f, m1r = -1e30f, l0 = 0.f, l1 = 0.f;

    int stg = 0;                 // stage buffer of tile t
    for (int t = 0; t < nT; t++) {
        CP_WAIT1();              // stage t guaranteed (always-commit invariant)
        __syncthreads();
        if (t + 2 < nT) {
            int nstg = stg - 1; if (nstg < 0) nstg = 2;   // (t+2) % 3
            load_kv(t + 2, nstg);
        }
        CP_COMMIT();
        const uint32_t st = sb + stg * FSTAGE;
        const int k0 = t * 64;

        // ---- S = Q K^T (single fp16)
        float s[4][2][4];
        #pragma unroll
        for (int i = 0; i < 4; i++)
            #pragma unroll
            for (int j = 0; j < 2; j++)
                #pragma unroll
                for (int k = 0; k < 4; k++) s[i][j][k] = 0.f;

        #pragma unroll
        for (int ds = 0; ds < 4; ds++) {
            uint32_t qh[4];
            LDM4(qh, sb + FQ + (wid * 16 + rowsel) * FP + ds * 32 + kg);
            #pragma unroll
            for (int nt = 0; nt < 4; nt++) {
                uint32_t bh[4];
                LDM4(bh, st + FK + (nt * 16 + rowsel) * FP + ds * 32 + kg);
                #pragma unroll
                for (int sub = 0; sub < 2; sub++)
                    MMA_F16(s[nt][sub], qh, bh[sub], bh[2 + sub]);
            }
        }

        // ---- causal mask (last two tiles)
        if (t >= nT - 2) {
            #pragma unroll
            for (int nt = 0; nt < 4; nt++)
                #pragma unroll
                for (int sub = 0; sub < 2; sub++) {
                    int colb = k0 + nt * 16 + sub * 8 + (lane & 3) * 2;
                    if (colb     > row0)     s[nt][sub][0] = -1e30f;
                    if (colb + 1 > row0)     s[nt][sub][1] = -1e30f;
                    if (colb     > row0 + 8) s[nt][sub][2] = -1e30f;
                    if (colb + 1 > row0 + 8) s[nt][sub][3] = -1e30f;
                }
        }

        // ---- online softmax (exp2 domain)
        float mx0 = -1e30f, mx1 = -1e30f;
        #pragma unroll
        for (int nt = 0; nt < 4; nt++)
            #pragma unroll
            for (int sub = 0; sub < 2; sub++) {
                mx0 = fmaxf(mx0, fmaxf(s[nt][sub][0], s[nt][sub][1]));
                mx1 = fmaxf(mx1, fmaxf(s[nt][sub][2], s[nt][sub][3]));
            }
        mx0 = fmaxf(mx0, __shfl_xor_sync(0xffffffffu, mx0, 1));
        mx0 = fmaxf(mx0, __shfl_xor_sync(0xffffffffu, mx0, 2));
        mx1 = fmaxf(mx1, __shfl_xor_sync(0xffffffffu, mx1, 1));
        mx1 = fmaxf(mx1, __shfl_xor_sync(0xffffffffu, mx1, 2));
        float nm0 = fmaxf(m0r, mx0), nm1 = fmaxf(m1r, mx1);
        float c0 = exp2_fast(m0r - nm0), c1 = exp2_fast(m1r - nm1);
        m0r = nm0; m1r = nm1;

        float rs0 = 0.f, rs1 = 0.f;
        uint32_t pa[4][4];
        #pragma unroll
        for (int kc = 0; kc < 4; kc++) {
            #pragma unroll
            for (int sub = 0; sub < 2; sub++) {
                float p0 = exp2_fast(s[kc][sub][0] - nm0);
                float p1 = exp2_fast(s[kc][sub][1] - nm0);
                float p2 = exp2_fast(s[kc][sub][2] - nm1);
                float p3 = exp2_fast(s[kc][sub][3] - nm1);
                rs0 += p0 + p1;
                rs1 += p2 + p3;
                pa[kc][sub * 2 + 0] = pack2h(p0, p1);
                pa[kc][sub * 2 + 1] = pack2h(p2, p3);
            }
        }
        rs0 += __shfl_xor_sync(0xffffffffu, rs0, 1);
        rs0 += __shfl_xor_sync(0xffffffffu, rs0, 2);
        rs1 += __shfl_xor_sync(0xffffffffu, rs1, 1);
        rs1 += __shfl_xor_sync(0xffffffffu, rs1, 2);
        l0 = l0 * c0 + rs0;
        l1 = l1 * c1 + rs1;

        #pragma unroll
        for (int dt = 0; dt < 4; dt++)
            #pragma unroll
            for (int sub = 0; sub < 2; sub++) {
                o[dt][sub][0] *= c0; o[dt][sub][1] *= c0;
                o[dt][sub][2] *= c1; o[dt][sub][3] *= c1;
            }

        // ---- O += P V (single fp16)
        #pragma unroll
        for (int kc = 0; kc < 4; kc++) {
            #pragma unroll
            for (int dt = 0; dt < 4; dt++) {
                uint32_t vh[4];
                LDM4T(vh, st + FV + kc * 16 * FP + dt * 32 + vlanebase);
                #pragma unroll
                for (int sub = 0; sub < 2; sub++)
                    MMA_F16(o[dt][sub], pa[kc], vh[2 * sub], vh[2 * sub + 1]);
            }
        }
        stg = (stg == 2) ? 0 : stg + 1;
    }

    // ---- write O as single fp16 (GEMM2 A-operand)
    const float inv0 = 1.0f / l0, inv1 = 1.0f / l1;
    const size_t obase = (size_t)(b * S_LEN) * D_MODEL + h * HD + (lane & 3) * 2;
    #pragma unroll
    for (int dt = 0; dt < 4; dt++)
        #pragma unroll
        for (int sub = 0; sub < 2; sub++) {
            int d = dt * 16 + sub * 8;
            uint32_t h0 = pack2h(o[dt][sub][0] * inv0, o[dt][sub][1] * inv0);
            uint32_t h1 = pack2h(o[dt][sub][2] * inv1, o[dt][sub][3] * inv1);
            *(uint32_t*)(g_o_h + obase + (size_t)row0 * D_MODEL + d)       = h0;
            *(uint32_t*)(g_o_h + obase + (size_t)(row0 + 8) * D_MODEL + d) = h1;
        }
}

// ---------------------------------------------------------------- launcher
extern "C" void kernel_launch(void* const* d_in, const int* in_sizes, int n_in,
                              void* d_out, int out_size) {
    const float* x        = (const float*)d_in[0];
    const float* c_attn_w = (const float*)d_in[1];
    const float* c_attn_b = (const float*)d_in[2];
    const float* c_proj_w = (const float*)d_in[3];
    const float* c_proj_b = (const float*)d_in[4];
    const float* q_a1     = (const float*)d_in[5];
    const float* q_a2     = (const float*)d_in[6];
    const float* v_a1     = (const float*)d_in[7];
    const float* v_a2     = (const float*)d_in[8];

    float* out     = (float*)d_out;
    float* a_out   = out;
    float* present = out + (size_t)ROWS * D_MODEL;

    __half *xh, *wh, *ph, *oh;
    cudaGetSymbolAddress((void**)&xh, g_x_h);
    cudaGetSymbolAddress((void**)&wh, g_wT_h);
    cudaGetSymbolAddress((void**)&ph, g_pT_h);
    cudaGetSymbolAddress((void**)&oh, g_o_h);

    cudaFuncSetAttribute(mma_gemm_h<0>, cudaFuncAttributeMaxDynamicSharedMemorySize, G_SMEM);
    cudaFuncSetAttribute(mma_gemm_h<1>, cudaFuncAttributeMaxDynamicSharedMemorySize, G_SMEM);
    cudaFuncSetAttribute(flash_mma, cudaFuncAttributeMaxDynamicSharedMemorySize, F_SMEM);

    // 1) operand prep
    build_weffT_h<<<dim3(N3 / 32, D_MODEL / 32), dim3(32, 32)>>>(c_attn_w, q_a1, q_a2, v_a1, v_a2);
    build_projT_h<<<dim3(D_MODEL / 32, D_MODEL / 32), dim3(32, 32)>>>(c_proj_w);
    split_x<<<(ROWS * D_MODEL / 4 + 255) / 256, 256>>>(x);

    // 2) qkv GEMM + fused epilogue
    mma_gemm_h<1><<<dim3(N3 / 128, ROWS / 128), 256, G_SMEM>>>(
        N3, D_MODEL, xh, wh, c_attn_b, nullptr, present);

    // 3) attention
    flash_mma<<<dim3(S_LEN / 128, B_SZ * N_HEADS), 256, F_SMEM>>>();

    // 4) output projection
    mma_gemm_h<0><<<dim3(D_MODEL / 128, ROWS / 128), 256, G_SMEM>>>(
        D_MODEL, D_MODEL, oh, ph, c_proj_b, a_out, nullptr);
}